// round 1
// baseline (speedup 1.0000x reference)
#include <cuda_runtime.h>
#include <math.h>

#define BATCH 2
#define SEQ   2048
#define DIM   512
#define NH    8
#define DH    64
#define NL    4
#define DFF   2048
#define WIN   256
#define BT    (BATCH*SEQ)   // 4096

// ---------------- scratch (static device globals; no allocation) -------------
__device__ float g_x  [BT*DIM];
__device__ float g_xn [BT*DIM];
__device__ float g_q  [BT*DIM];
__device__ float g_k  [BT*DIM];
__device__ float g_v  [BT*DIM];
__device__ float g_att[BT*DIM];
__device__ float g_h  [BT*DFF];

// ---------------- LayerNorm: one block per row (D=512), 256 threads ----------
__global__ void ln_kernel(const float* __restrict__ x, const float* __restrict__ g,
                          const float* __restrict__ b, float* __restrict__ y)
{
    int row = blockIdx.x;
    int tid = threadIdx.x;
    const float* xr = x + (size_t)row * DIM;

    float v0 = xr[tid];
    float v1 = xr[tid + 256];
    float s  = v0 + v1;
    float ss = v0 * v0 + v1 * v1;
    #pragma unroll
    for (int o = 16; o; o >>= 1) {
        s  += __shfl_xor_sync(0xffffffffu, s,  o);
        ss += __shfl_xor_sync(0xffffffffu, ss, o);
    }
    __shared__ float ws[8], wss[8];
    int w = tid >> 5, ln = tid & 31;
    if (ln == 0) { ws[w] = s; wss[w] = ss; }
    __syncthreads();
    __shared__ float s_mu, s_rstd;
    if (tid == 0) {
        float S = 0.f, SS = 0.f;
        #pragma unroll
        for (int i = 0; i < 8; i++) { S += ws[i]; SS += wss[i]; }
        float mu  = S * (1.0f / DIM);
        float var = SS * (1.0f / DIM) - mu * mu;
        s_mu = mu; s_rstd = rsqrtf(var + 1e-5f);
    }
    __syncthreads();
    float mu = s_mu, rstd = s_rstd;
    float* yr = y + (size_t)row * DIM;
    yr[tid]       = (v0 - mu) * rstd * g[tid]       + b[tid];
    yr[tid + 256] = (v1 - mu) * rstd * g[tid + 256] + b[tid + 256];
}

// ---------------- GEMM: C[M,N] = A[M,K] @ B[K,N] + bias (+gelu / +residual) ---
// EPI: 0 = bias only, 1 = bias + exact GELU, 2 = bias + residual add
#define GBM 64
#define GBN 64
#define GBK 16

template <int EPI>
__global__ void __launch_bounds__(256)
gemm_kernel(const float* __restrict__ A, const float* __restrict__ Bm,
            const float* __restrict__ bias, const float* __restrict__ res,
            float* __restrict__ C, int M, int N, int K)
{
    __shared__ float As[GBK][GBM + 4];   // k-major, row stride 68 floats (16B-aligned per k)
    __shared__ float Bs[GBK][GBN + 4];

    int tid = threadIdx.x;
    int tx = tid & 15;        // 0..15 -> N
    int ty = tid >> 4;        // 0..15 -> M
    int m0 = blockIdx.y * GBM;
    int n0 = blockIdx.x * GBN;

    const float* Ab = A  + (size_t)m0 * K;
    const float* Bb = Bm + n0;

    float acc[4][4];
    #pragma unroll
    for (int i = 0; i < 4; i++)
        #pragma unroll
        for (int j = 0; j < 4; j++) acc[i][j] = 0.f;

    for (int k0 = 0; k0 < K; k0 += GBK) {
        // load A tile 64x16 (coalesced in 16-wide rows)
        #pragma unroll
        for (int s = 0; s < 4; s++) {
            int idx = tid + 256 * s;
            int r = idx >> 4, c = idx & 15;
            As[c][r] = Ab[(size_t)r * K + k0 + c];
        }
        // load B tile 16x64 (fully coalesced)
        #pragma unroll
        for (int s = 0; s < 4; s++) {
            int idx = tid + 256 * s;
            int r = idx >> 6, c = idx & 63;
            Bs[r][c] = Bb[(size_t)(k0 + r) * N + c];
        }
        __syncthreads();

        #pragma unroll
        for (int kk = 0; kk < GBK; kk++) {
            float4 a4 = *reinterpret_cast<const float4*>(&As[kk][ty * 4]);
            float4 b4 = *reinterpret_cast<const float4*>(&Bs[kk][tx * 4]);
            float a[4] = {a4.x, a4.y, a4.z, a4.w};
            float b[4] = {b4.x, b4.y, b4.z, b4.w};
            #pragma unroll
            for (int i = 0; i < 4; i++)
                #pragma unroll
                for (int j = 0; j < 4; j++)
                    acc[i][j] += a[i] * b[j];
        }
        __syncthreads();
    }

    #pragma unroll
    for (int i = 0; i < 4; i++) {
        int row = m0 + ty * 4 + i;
        #pragma unroll
        for (int j = 0; j < 4; j++) {
            int col = n0 + tx * 4 + j;
            float cval = acc[i][j] + bias[col];
            if (EPI == 1) {
                cval = 0.5f * cval * (1.0f + erff(cval * 0.70710678118654752f));
            }
            if (EPI == 2) {
                cval += res[(size_t)row * N + col];
            }
            C[(size_t)row * N + col] = cval;
        }
    }
}

// ---------------- RoPE (applied in-place to q and k) --------------------------
// pair index: d in [0,32); out[d] = x[d]*c - x[d+32]*s ; out[d+32] = x[d+32]*c + x[d]*s
__global__ void rope_kernel(float* __restrict__ q, float* __restrict__ k)
{
    int idx = blockIdx.x * blockDim.x + threadIdx.x;   // over BT*NH*32
    int d  = idx & 31;
    int h  = (idx >> 5) & (NH - 1);
    int bt = idx >> 8;            // 32*8 = 256 per token
    int t  = bt & (SEQ - 1);

    float inv_freq = powf(10000.0f, -(float)(2 * d) / (float)DH);
    float ang = (float)t * inv_freq;
    float c, s;
    sincosf(ang, &s, &c);

    size_t base = (size_t)bt * DIM + h * DH + d;

    float q1 = q[base], q2 = q[base + 32];
    q[base]      = q1 * c - q2 * s;
    q[base + 32] = q2 * c + q1 * s;

    float k1 = k[base], k2 = k[base + 32];
    k[base]      = k1 * c - k2 * s;
    k[base + 32] = k2 * c + k1 * s;
}

// ---------------- Sliding-window causal attention ----------------------------
// One 256-thread block per (b, h, query i). keys j in [max(0,i-WIN+1), i] (<=256).
__global__ void __launch_bounds__(256)
attn_kernel(const float* __restrict__ q, const float* __restrict__ k,
            const float* __restrict__ v, float* __restrict__ out)
{
    int gid = blockIdx.x;                 // i + SEQ*(h + NH*b)
    int i = gid & (SEQ - 1);
    int h = (gid >> 11) & (NH - 1);
    int b = gid >> 14;
    int tid = threadIdx.x;

    int j0  = (i - WIN + 1 > 0) ? (i - WIN + 1) : 0;
    int cnt = i - j0 + 1;                 // 1..256

    __shared__ float sq[DH];
    __shared__ float sp[256];
    __shared__ float red[256];
    __shared__ float acc4[4][DH];

    if (tid < DH)
        sq[tid] = q[(size_t)(b * SEQ + i) * DIM + h * DH + tid] * 0.125f; // 1/sqrt(64)
    __syncthreads();

    // scores
    float sc = -INFINITY;
    if (tid < cnt) {
        const float* krow = k + (size_t)(b * SEQ + j0 + tid) * DIM + h * DH;
        float a = 0.f;
        #pragma unroll
        for (int d = 0; d < DH; d += 4) {
            float4 kk = *reinterpret_cast<const float4*>(krow + d);
            a += sq[d] * kk.x + sq[d + 1] * kk.y + sq[d + 2] * kk.z + sq[d + 3] * kk.w;
        }
        sc = a;
    }

    // block max
    red[tid] = sc;
    __syncthreads();
    #pragma unroll
    for (int o = 128; o; o >>= 1) {
        if (tid < o) red[tid] = fmaxf(red[tid], red[tid + o]);
        __syncthreads();
    }
    float m = red[0];
    __syncthreads();

    float p = (tid < cnt) ? expf(sc - m) : 0.f;
    sp[tid]  = p;
    red[tid] = p;
    __syncthreads();
    #pragma unroll
    for (int o = 128; o; o >>= 1) {
        if (tid < o) red[tid] += red[tid + o];
        __syncthreads();
    }
    float ssum = red[0];
    // sp[] is stable from here; no further writes before final read

    // P @ V : 4 groups of 64 threads split the key range
    int grp = tid >> 6;
    int d   = tid & 63;
    float a = 0.f;
    for (int j = grp; j < cnt; j += 4)
        a += sp[j] * v[(size_t)(b * SEQ + j0 + j) * DIM + h * DH + d];
    acc4[grp][d] = a;
    __syncthreads();

    if (tid < DH) {
        float o = (acc4[0][tid] + acc4[1][tid] + acc4[2][tid] + acc4[3][tid]) / ssum;
        out[(size_t)(b * SEQ + i) * DIM + h * DH + tid] = o;
    }
}

// ---------------- host launcher ----------------------------------------------
extern "C" void kernel_launch(void* const* d_in, const int* in_sizes, int n_in,
                              void* d_out, int out_size)
{
    const float* tokens = (const float*)d_in[0];
    const float* Wq = (const float*)d_in[1];
    const float* Wk = (const float*)d_in[2];
    const float* Wv = (const float*)d_in[3];
    const float* Wo = (const float*)d_in[4];
    const float* bq = (const float*)d_in[5];
    const float* bk = (const float*)d_in[6];
    const float* bv = (const float*)d_in[7];
    const float* bo = (const float*)d_in[8];
    const float* W1 = (const float*)d_in[9];
    const float* b1 = (const float*)d_in[10];
    const float* W2 = (const float*)d_in[11];
    const float* b2 = (const float*)d_in[12];
    const float* g1 = (const float*)d_in[13];
    const float* be1= (const float*)d_in[14];
    const float* g2 = (const float*)d_in[15];
    const float* be2= (const float*)d_in[16];
    const float* gf = (const float*)d_in[17];
    const float* bf = (const float*)d_in[18];

    float *x, *xn, *q, *k, *v, *att, *hb;
    cudaGetSymbolAddress((void**)&x,   g_x);
    cudaGetSymbolAddress((void**)&xn,  g_xn);
    cudaGetSymbolAddress((void**)&q,   g_q);
    cudaGetSymbolAddress((void**)&k,   g_k);
    cudaGetSymbolAddress((void**)&v,   g_v);
    cudaGetSymbolAddress((void**)&att, g_att);
    cudaGetSymbolAddress((void**)&hb,  g_h);

    cudaMemcpyAsync(x, tokens, sizeof(float) * (size_t)BT * DIM,
                    cudaMemcpyDeviceToDevice, 0);

    dim3 gD (DIM / GBN, BT / GBM);   // N=512 GEMMs
    dim3 gF (DFF / GBN, BT / GBM);   // N=2048 GEMM

    for (int l = 0; l < NL; l++) {
        const float* Wql = Wq + (size_t)l * DIM * DIM;
        const float* Wkl = Wk + (size_t)l * DIM * DIM;
        const float* Wvl = Wv + (size_t)l * DIM * DIM;
        const float* Wol = Wo + (size_t)l * DIM * DIM;
        const float* W1l = W1 + (size_t)l * DIM * DFF;
        const float* W2l = W2 + (size_t)l * DFF * DIM;

        ln_kernel<<<BT, 256>>>(x, g1 + l * DIM, be1 + l * DIM, xn);

        gemm_kernel<0><<<gD, 256>>>(xn, Wql, bq + l * DIM, nullptr, q, BT, DIM, DIM);
        gemm_kernel<0><<<gD, 256>>>(xn, Wkl, bk + l * DIM, nullptr, k, BT, DIM, DIM);
        gemm_kernel<0><<<gD, 256>>>(xn, Wvl, bv + l * DIM, nullptr, v, BT, DIM, DIM);

        rope_kernel<<<(BT * NH * 32) / 256, 256>>>(q, k);

        attn_kernel<<<BATCH * NH * SEQ, 256>>>(q, k, v, att);

        gemm_kernel<2><<<gD, 256>>>(att, Wol, bo + l * DIM, x, x, BT, DIM, DIM);

        ln_kernel<<<BT, 256>>>(x, g2 + l * DIM, be2 + l * DIM, xn);

        gemm_kernel<1><<<gF, 256>>>(xn, W1l, b1 + l * DFF, nullptr, hb, BT, DFF, DIM);
        gemm_kernel<2><<<gD, 256>>>(hb, W2l, b2 + l * DIM, x, x, BT, DIM, DFF);
    }

    ln_kernel<<<BT, 256>>>(x, gf, bf, (float*)d_out);
}

// round 2
// speedup vs baseline: 1.2743x; 1.2743x over previous
#include <cuda_runtime.h>
#include <math.h>

#define BATCH 2
#define SEQ   2048
#define DIM   512
#define NH    8
#define DH    64
#define NL    4
#define DFF   2048
#define WIN   256
#define BT    (BATCH*SEQ)   // 4096

// ---------------- scratch (static device globals; no allocation) -------------
__device__ float g_x  [BT*DIM];
__device__ float g_xn [BT*DIM];
__device__ float g_q  [BT*DIM];
__device__ float g_k  [BT*DIM];
__device__ float g_v  [BT*DIM];
__device__ float g_att[BT*DIM];
__device__ float g_h  [BT*DFF];

// ---------------- LayerNorm: one block per row (D=512), 256 threads ----------
__global__ void ln_kernel(const float* __restrict__ x, const float* __restrict__ g,
                          const float* __restrict__ b, float* __restrict__ y)
{
    int row = blockIdx.x;
    int tid = threadIdx.x;
    const float* xr = x + (size_t)row * DIM;

    float v0 = xr[tid];
    float v1 = xr[tid + 256];
    float s  = v0 + v1;
    float ss = v0 * v0 + v1 * v1;
    #pragma unroll
    for (int o = 16; o; o >>= 1) {
        s  += __shfl_xor_sync(0xffffffffu, s,  o);
        ss += __shfl_xor_sync(0xffffffffu, ss, o);
    }
    __shared__ float ws[8], wss[8];
    int w = tid >> 5, ln = tid & 31;
    if (ln == 0) { ws[w] = s; wss[w] = ss; }
    __syncthreads();
    __shared__ float s_mu, s_rstd;
    if (tid == 0) {
        float S = 0.f, SS = 0.f;
        #pragma unroll
        for (int i = 0; i < 8; i++) { S += ws[i]; SS += wss[i]; }
        float mu  = S * (1.0f / DIM);
        float var = SS * (1.0f / DIM) - mu * mu;
        s_mu = mu; s_rstd = rsqrtf(var + 1e-5f);
    }
    __syncthreads();
    float mu = s_mu, rstd = s_rstd;
    float* yr = y + (size_t)row * DIM;
    yr[tid]       = (v0 - mu) * rstd * g[tid]       + b[tid];
    yr[tid + 256] = (v1 - mu) * rstd * g[tid + 256] + b[tid + 256];
}

// ---------------- GEMM: C[M,N] = A[M,K] @ B[K,N] + bias (+gelu / +residual) ---
// 128x128x16 tile, 256 threads, 8x8 microtile. 1 byte smem per FMA.
// EPI: 0 = bias only, 1 = bias + exact GELU, 2 = bias + residual add
#define GBM 128
#define GBN 128
#define GBK 16

template <int EPI>
__global__ void __launch_bounds__(256, 2)
gemm_kernel(const float* __restrict__ A, const float* __restrict__ Bm,
            const float* __restrict__ bias, const float* __restrict__ res,
            float* __restrict__ C, int M, int N, int K)
{
    __shared__ float As[GBK][GBM + 4];   // k-major (transposed A tile)
    __shared__ float Bs[GBK][GBN + 4];

    int tid = threadIdx.x;
    int tx = tid & 15;        // 0..15 -> N (8 cols each)
    int ty = tid >> 4;        // 0..15 -> M (8 rows each)
    int m0 = blockIdx.y * GBM;
    int n0 = blockIdx.x * GBN;

    const float* Ab = A  + (size_t)m0 * K;
    const float* Bb = Bm + n0;

    float acc[8][8];
    #pragma unroll
    for (int i = 0; i < 8; i++)
        #pragma unroll
        for (int j = 0; j < 8; j++) acc[i][j] = 0.f;

    for (int k0 = 0; k0 < K; k0 += GBK) {
        // A tile 128x16 -> As transposed
        #pragma unroll
        for (int s = 0; s < 8; s++) {
            int idx = tid + 256 * s;
            int r = idx >> 4, c = idx & 15;
            As[c][r] = Ab[(size_t)r * K + k0 + c];
        }
        // B tile 16x128 (fully coalesced)
        #pragma unroll
        for (int s = 0; s < 8; s++) {
            int idx = tid + 256 * s;
            int r = idx >> 7, c = idx & 127;
            Bs[r][c] = Bb[(size_t)(k0 + r) * N + c];
        }
        __syncthreads();

        #pragma unroll
        for (int kk = 0; kk < GBK; kk++) {
            float a[8], b[8];
            float4 a0 = *reinterpret_cast<const float4*>(&As[kk][ty * 8]);
            float4 a1 = *reinterpret_cast<const float4*>(&As[kk][ty * 8 + 4]);
            float4 b0 = *reinterpret_cast<const float4*>(&Bs[kk][tx * 8]);
            float4 b1 = *reinterpret_cast<const float4*>(&Bs[kk][tx * 8 + 4]);
            a[0]=a0.x; a[1]=a0.y; a[2]=a0.z; a[3]=a0.w;
            a[4]=a1.x; a[5]=a1.y; a[6]=a1.z; a[7]=a1.w;
            b[0]=b0.x; b[1]=b0.y; b[2]=b0.z; b[3]=b0.w;
            b[4]=b1.x; b[5]=b1.y; b[6]=b1.z; b[7]=b1.w;
            #pragma unroll
            for (int i = 0; i < 8; i++)
                #pragma unroll
                for (int j = 0; j < 8; j++)
                    acc[i][j] += a[i] * b[j];
        }
        __syncthreads();
    }

    // epilogue
    float4 bv0 = *reinterpret_cast<const float4*>(bias + n0 + tx * 8);
    float4 bv1 = *reinterpret_cast<const float4*>(bias + n0 + tx * 8 + 4);
    float bb[8] = {bv0.x, bv0.y, bv0.z, bv0.w, bv1.x, bv1.y, bv1.z, bv1.w};

    #pragma unroll
    for (int i = 0; i < 8; i++) {
        int row = m0 + ty * 8 + i;
        float out[8];
        #pragma unroll
        for (int j = 0; j < 8; j++) {
            float cval = acc[i][j] + bb[j];
            if (EPI == 1)
                cval = 0.5f * cval * (1.0f + erff(cval * 0.70710678118654752f));
            out[j] = cval;
        }
        size_t base = (size_t)row * N + n0 + tx * 8;
        if (EPI == 2) {
            float4 r0 = *reinterpret_cast<const float4*>(res + base);
            float4 r1 = *reinterpret_cast<const float4*>(res + base + 4);
            out[0]+=r0.x; out[1]+=r0.y; out[2]+=r0.z; out[3]+=r0.w;
            out[4]+=r1.x; out[5]+=r1.y; out[6]+=r1.z; out[7]+=r1.w;
        }
        *reinterpret_cast<float4*>(C + base)     = make_float4(out[0], out[1], out[2], out[3]);
        *reinterpret_cast<float4*>(C + base + 4) = make_float4(out[4], out[5], out[6], out[7]);
    }
}

// ---------------- RoPE (applied in-place to q and k) --------------------------
__global__ void rope_kernel(float* __restrict__ q, float* __restrict__ k)
{
    int idx = blockIdx.x * blockDim.x + threadIdx.x;   // over BT*NH*32
    int d  = idx & 31;
    int h  = (idx >> 5) & (NH - 1);
    int bt = idx >> 8;
    int t  = bt & (SEQ - 1);

    float inv_freq = powf(10000.0f, -(float)(2 * d) / (float)DH);
    float ang = (float)t * inv_freq;
    float c, s;
    sincosf(ang, &s, &c);

    size_t base = (size_t)bt * DIM + h * DH + d;

    float q1 = q[base], q2 = q[base + 32];
    q[base]      = q1 * c - q2 * s;
    q[base + 32] = q2 * c + q1 * s;

    float k1 = k[base], k2 = k[base + 32];
    k[base]      = k1 * c - k2 * s;
    k[base + 32] = k2 * c + k1 * s;
}

// ---------------- Flash-style sliding-window attention ------------------------
// Block = 64 consecutive queries of one (b,h). Keys span [t0-256, t0+63] = 5
// tiles of 64. Full S (64x320) kept in smem -> simple two-pass softmax.
#define QT    64
#define KSPAN 320
#define SPAD  324

// smem layout (floats): Qs[64][68] | KV[64][68] | S[64][324] | linv[64]
#define SM_QS   0
#define SM_KV   (64*68)
#define SM_S    (2*64*68)
#define SM_LINV (2*64*68 + 64*SPAD)
#define ATT_SMEM_FLOATS (2*64*68 + 64*SPAD + 64)

__global__ void __launch_bounds__(256)
attn_kernel(const float* __restrict__ q, const float* __restrict__ k,
            const float* __restrict__ v, float* __restrict__ out)
{
    extern __shared__ float sm[];
    float* Qs   = sm + SM_QS;    // d-major: Qs[d*68 + r]
    float* KV   = sm + SM_KV;    // K: d-major KV[d*68+c]; V: k-major KV[kk*68+c]
    float* S    = sm + SM_S;     // S[r*324 + cc]
    float* linv = sm + SM_LINV;

    int tid = threadIdx.x;
    int t0  = blockIdx.x * QT;
    int bh  = blockIdx.y;
    int b   = bh >> 3;
    int h   = bh & 7;
    int jbase = t0 - 256;

    int tx = tid & 15, ty = tid >> 4;
    int r0 = ty * 4, c0 = tx * 4;

    // load Q tile transposed, pre-scaled by 1/sqrt(DH)
    #pragma unroll
    for (int s = 0; s < 16; s++) {
        int idx = tid + 256 * s;
        int d = idx & 63, r = idx >> 6;
        Qs[d * 68 + r] = q[(size_t)(b * SEQ + t0 + r) * DIM + h * DH + d] * 0.125f;
    }

    // ---- scores: 5 K-tiles ----
    for (int s = 0; s < 5; s++) {
        int kb = jbase + s * 64;
        __syncthreads();
        #pragma unroll
        for (int it = 0; it < 16; it++) {
            int idx = tid + 256 * it;
            int d = idx & 63, c = idx >> 6;
            int j = kb + c;
            int jc = j < 0 ? 0 : j;          // clamp (masked later)
            KV[d * 68 + c] = k[(size_t)(b * SEQ + jc) * DIM + h * DH + d];
        }
        __syncthreads();

        float acc[4][4];
        #pragma unroll
        for (int i = 0; i < 4; i++)
            #pragma unroll
            for (int j = 0; j < 4; j++) acc[i][j] = 0.f;

        #pragma unroll 8
        for (int d = 0; d < DH; d++) {
            float4 a4 = *reinterpret_cast<const float4*>(&Qs[d * 68 + r0]);
            float4 b4 = *reinterpret_cast<const float4*>(&KV[d * 68 + c0]);
            float a[4] = {a4.x, a4.y, a4.z, a4.w};
            float bb[4] = {b4.x, b4.y, b4.z, b4.w};
            #pragma unroll
            for (int i = 0; i < 4; i++)
                #pragma unroll
                for (int j = 0; j < 4; j++)
                    acc[i][j] += a[i] * bb[j];
        }

        #pragma unroll
        for (int i = 0; i < 4; i++) {
            int ig = t0 + r0 + i;
            #pragma unroll
            for (int j = 0; j < 4; j++) {
                int jg = kb + c0 + j;
                bool ok = (jg >= 0) && (jg <= ig) && (ig - jg < WIN);
                S[(r0 + i) * SPAD + s * 64 + c0 + j] = ok ? acc[i][j] : -INFINITY;
            }
        }
    }
    __syncthreads();

    // ---- softmax over 320 cols; 4 threads per row ----
    {
        int r = tid >> 2, p = tid & 3;
        float m = -INFINITY;
        for (int cc = p; cc < KSPAN; cc += 4) m = fmaxf(m, S[r * SPAD + cc]);
        m = fmaxf(m, __shfl_xor_sync(0xffffffffu, m, 1));
        m = fmaxf(m, __shfl_xor_sync(0xffffffffu, m, 2));
        float sum = 0.f;
        for (int cc = p; cc < KSPAN; cc += 4) {
            float e = __expf(S[r * SPAD + cc] - m);
            S[r * SPAD + cc] = e;
            sum += e;
        }
        sum += __shfl_xor_sync(0xffffffffu, sum, 1);
        sum += __shfl_xor_sync(0xffffffffu, sum, 2);
        if (p == 0) linv[r] = 1.0f / sum;
    }

    // ---- O = P @ V ----
    float o[4][4];
    #pragma unroll
    for (int i = 0; i < 4; i++)
        #pragma unroll
        for (int j = 0; j < 4; j++) o[i][j] = 0.f;

    for (int s = 0; s < 5; s++) {
        int kb = jbase + s * 64;
        __syncthreads();
        #pragma unroll
        for (int it = 0; it < 16; it++) {
            int idx = tid + 256 * it;
            int c = idx & 63, kk = idx >> 6;
            int j = kb + kk;
            int jc = j < 0 ? 0 : j;
            KV[kk * 68 + c] = v[(size_t)(b * SEQ + jc) * DIM + h * DH + c];
        }
        __syncthreads();

        #pragma unroll 8
        for (int kk = 0; kk < 64; kk++) {
            float4 v4 = *reinterpret_cast<const float4*>(&KV[kk * 68 + c0]);
            float vv[4] = {v4.x, v4.y, v4.z, v4.w};
            float pp[4];
            #pragma unroll
            for (int i = 0; i < 4; i++)
                pp[i] = S[(r0 + i) * SPAD + s * 64 + kk];
            #pragma unroll
            for (int i = 0; i < 4; i++)
                #pragma unroll
                for (int j = 0; j < 4; j++)
                    o[i][j] += pp[i] * vv[j];
        }
    }

    #pragma unroll
    for (int i = 0; i < 4; i++) {
        float li = linv[r0 + i];
        #pragma unroll
        for (int j = 0; j < 4; j++)
            out[(size_t)(b * SEQ + t0 + r0 + i) * DIM + h * DH + c0 + j] = o[i][j] * li;
    }
}

// ---------------- host launcher ----------------------------------------------
extern "C" void kernel_launch(void* const* d_in, const int* in_sizes, int n_in,
                              void* d_out, int out_size)
{
    const float* tokens = (const float*)d_in[0];
    const float* Wq = (const float*)d_in[1];
    const float* Wk = (const float*)d_in[2];
    const float* Wv = (const float*)d_in[3];
    const float* Wo = (const float*)d_in[4];
    const float* bq = (const float*)d_in[5];
    const float* bk = (const float*)d_in[6];
    const float* bv = (const float*)d_in[7];
    const float* bo = (const float*)d_in[8];
    const float* W1 = (const float*)d_in[9];
    const float* b1 = (const float*)d_in[10];
    const float* W2 = (const float*)d_in[11];
    const float* b2 = (const float*)d_in[12];
    const float* g1 = (const float*)d_in[13];
    const float* be1= (const float*)d_in[14];
    const float* g2 = (const float*)d_in[15];
    const float* be2= (const float*)d_in[16];
    const float* gf = (const float*)d_in[17];
    const float* bf = (const float*)d_in[18];

    float *x, *xn, *q, *k, *v, *att, *hb;
    cudaGetSymbolAddress((void**)&x,   g_x);
    cudaGetSymbolAddress((void**)&xn,  g_xn);
    cudaGetSymbolAddress((void**)&q,   g_q);
    cudaGetSymbolAddress((void**)&k,   g_k);
    cudaGetSymbolAddress((void**)&v,   g_v);
    cudaGetSymbolAddress((void**)&att, g_att);
    cudaGetSymbolAddress((void**)&hb,  g_h);

    static const size_t att_smem = ATT_SMEM_FLOATS * sizeof(float);
    cudaFuncSetAttribute(attn_kernel, cudaFuncAttributeMaxDynamicSharedMemorySize,
                         (int)att_smem);

    cudaMemcpyAsync(x, tokens, sizeof(float) * (size_t)BT * DIM,
                    cudaMemcpyDeviceToDevice, 0);

    dim3 gD (DIM / GBN, BT / GBM);   // (4, 32)  N=512 GEMMs
    dim3 gF (DFF / GBN, BT / GBM);   // (16, 32) N=2048 GEMM
    dim3 gAtt(SEQ / QT, BATCH * NH); // (32, 16)

    for (int l = 0; l < NL; l++) {
        const float* Wql = Wq + (size_t)l * DIM * DIM;
        const float* Wkl = Wk + (size_t)l * DIM * DIM;
        const float* Wvl = Wv + (size_t)l * DIM * DIM;
        const float* Wol = Wo + (size_t)l * DIM * DIM;
        const float* W1l = W1 + (size_t)l * DIM * DFF;
        const float* W2l = W2 + (size_t)l * DFF * DIM;

        ln_kernel<<<BT, 256>>>(x, g1 + l * DIM, be1 + l * DIM, xn);

        gemm_kernel<0><<<gD, 256>>>(xn, Wql, bq + l * DIM, nullptr, q, BT, DIM, DIM);
        gemm_kernel<0><<<gD, 256>>>(xn, Wkl, bk + l * DIM, nullptr, k, BT, DIM, DIM);
        gemm_kernel<0><<<gD, 256>>>(xn, Wvl, bv + l * DIM, nullptr, v, BT, DIM, DIM);

        rope_kernel<<<(BT * NH * 32) / 256, 256>>>(q, k);

        attn_kernel<<<gAtt, 256, att_smem>>>(q, k, v, att);

        gemm_kernel<2><<<gD, 256>>>(att, Wol, bo + l * DIM, x, x, BT, DIM, DIM);

        ln_kernel<<<BT, 256>>>(x, g2 + l * DIM, be2 + l * DIM, xn);

        gemm_kernel<1><<<gF, 256>>>(xn, W1l, b1 + l * DFF, nullptr, hb, BT, DFF, DIM);
        gemm_kernel<2><<<gD, 256>>>(hb, W2l, b2 + l * DIM, x, x, BT, DIM, DFF);
    }

    ln_kernel<<<BT, 256>>>(x, gf, bf, (float*)d_out);
}

// round 3
// speedup vs baseline: 1.7554x; 1.3776x over previous
#include <cuda_runtime.h>
#include <math.h>
#include <stdint.h>

#define BATCH 2
#define SEQ   2048
#define DIM   512
#define NH    8
#define DH    64
#define NL    4
#define DFF   2048
#define WIN   256
#define BT    (BATCH*SEQ)   // 4096

// ---------------- scratch (static device globals; no allocation) -------------
__device__ float g_x  [BT*DIM];
__device__ float g_xn [BT*DIM];
__device__ float g_q  [BT*DIM];
__device__ float g_k  [BT*DIM];
__device__ float g_v  [BT*DIM];
__device__ float g_att[BT*DIM];
__device__ float g_h  [BT*DFF];

// ---------------- LayerNorm ----------------------------------------------------
__global__ void ln_kernel(const float* __restrict__ x, const float* __restrict__ g,
                          const float* __restrict__ b, float* __restrict__ y)
{
    int row = blockIdx.x;
    int tid = threadIdx.x;
    const float* xr = x + (size_t)row * DIM;

    float v0 = xr[tid];
    float v1 = xr[tid + 256];
    float s  = v0 + v1;
    float ss = v0 * v0 + v1 * v1;
    #pragma unroll
    for (int o = 16; o; o >>= 1) {
        s  += __shfl_xor_sync(0xffffffffu, s,  o);
        ss += __shfl_xor_sync(0xffffffffu, ss, o);
    }
    __shared__ float ws[8], wss[8];
    int w = tid >> 5, ln = tid & 31;
    if (ln == 0) { ws[w] = s; wss[w] = ss; }
    __syncthreads();
    __shared__ float s_mu, s_rstd;
    if (tid == 0) {
        float S = 0.f, SS = 0.f;
        #pragma unroll
        for (int i = 0; i < 8; i++) { S += ws[i]; SS += wss[i]; }
        float mu  = S * (1.0f / DIM);
        float var = SS * (1.0f / DIM) - mu * mu;
        s_mu = mu; s_rstd = rsqrtf(var + 1e-5f);
    }
    __syncthreads();
    float mu = s_mu, rstd = s_rstd;
    float* yr = y + (size_t)row * DIM;
    yr[tid]       = (v0 - mu) * rstd * g[tid]       + b[tid];
    yr[tid + 256] = (v1 - mu) * rstd * g[tid + 256] + b[tid + 256];
}

// ---------------- GEMM core: cp.async double-buffered 128x128x16 --------------
#define GBM 128
#define GBN 128
#define GBK 16
#define APAD 20    // A row stride (floats), multiple of 4 for 16B cp.async
#define BPAD 132   // B row stride (floats)

__device__ __forceinline__ void cpa16(float* dst, const float* src)
{
    uint32_t s = (uint32_t)__cvta_generic_to_shared(dst);
    asm volatile("cp.async.cg.shared.global [%0], [%1], 16;" :: "r"(s), "l"(src));
}

// EPI: 0 = bias, 1 = bias+GELU(exact), 2 = bias+residual
template <int EPI>
__device__ __forceinline__ void gemm_core(
    const float* __restrict__ A, const float* __restrict__ Bm,
    const float* __restrict__ bias, const float* __restrict__ res,
    float* __restrict__ C, int N, int K, int m0, int n0)
{
    __shared__ float As[2][GBM * APAD];
    __shared__ float Bs[2][GBK * BPAD];

    int tid = threadIdx.x;
    int tx = tid & 15;     // cols: tx*4 .. +3 and tx*4+64 .. +3
    int ty = tid >> 4;     // rows: ty*8 .. +7

    const float* Ab = A + (size_t)m0 * K;
    const float* Bb = Bm + n0;

    float acc[8][8];
    #pragma unroll
    for (int i = 0; i < 8; i++)
        #pragma unroll
        for (int j = 0; j < 8; j++) acc[i][j] = 0.f;

    int nkt = K / GBK;

    // stage 0 prefetch
    {
        #pragma unroll
        for (int s = 0; s < 2; s++) {
            int idx = tid + 256 * s;
            int r = idx >> 2, q = (idx & 3) * 4;
            cpa16(&As[0][r * APAD + q], Ab + (size_t)r * K + q);
        }
        #pragma unroll
        for (int s = 0; s < 2; s++) {
            int idx = tid + 256 * s;
            int kr = idx >> 5, cq = (idx & 31) * 4;
            cpa16(&Bs[0][kr * BPAD + cq], Bb + (size_t)kr * N + cq);
        }
        asm volatile("cp.async.commit_group;");
    }

    for (int kt = 0; kt < nkt; kt++) {
        asm volatile("cp.async.wait_group 0;");
        __syncthreads();

        if (kt + 1 < nkt) {
            int buf = (kt + 1) & 1;
            int k0 = (kt + 1) * GBK;
            #pragma unroll
            for (int s = 0; s < 2; s++) {
                int idx = tid + 256 * s;
                int r = idx >> 2, q = (idx & 3) * 4;
                cpa16(&As[buf][r * APAD + q], Ab + (size_t)r * K + k0 + q);
            }
            #pragma unroll
            for (int s = 0; s < 2; s++) {
                int idx = tid + 256 * s;
                int kr = idx >> 5, cq = (idx & 31) * 4;
                cpa16(&Bs[buf][kr * BPAD + cq], Bb + (size_t)(k0 + kr) * N + cq);
            }
            asm volatile("cp.async.commit_group;");
        }

        const float* Asb = As[kt & 1];
        const float* Bsb = Bs[kt & 1];
        #pragma unroll
        for (int kk = 0; kk < GBK; kk++) {
            float a[8], b[8];
            #pragma unroll
            for (int i = 0; i < 8; i++)
                a[i] = Asb[(ty * 8 + i) * APAD + kk];
            float4 b0 = *reinterpret_cast<const float4*>(&Bsb[kk * BPAD + tx * 4]);
            float4 b1 = *reinterpret_cast<const float4*>(&Bsb[kk * BPAD + tx * 4 + 64]);
            b[0]=b0.x; b[1]=b0.y; b[2]=b0.z; b[3]=b0.w;
            b[4]=b1.x; b[5]=b1.y; b[6]=b1.z; b[7]=b1.w;
            #pragma unroll
            for (int i = 0; i < 8; i++)
                #pragma unroll
                for (int j = 0; j < 8; j++)
                    acc[i][j] += a[i] * b[j];
        }
    }

    // epilogue
    float4 bv0 = *reinterpret_cast<const float4*>(bias + n0 + tx * 4);
    float4 bv1 = *reinterpret_cast<const float4*>(bias + n0 + tx * 4 + 64);
    float bb[8] = {bv0.x, bv0.y, bv0.z, bv0.w, bv1.x, bv1.y, bv1.z, bv1.w};

    #pragma unroll
    for (int i = 0; i < 8; i++) {
        int row = m0 + ty * 8 + i;
        size_t base = (size_t)row * N + n0 + tx * 4;
        float o[8];
        #pragma unroll
        for (int j = 0; j < 8; j++) {
            float cval = acc[i][j] + bb[j];
            if (EPI == 1)
                cval = 0.5f * cval * (1.0f + erff(cval * 0.70710678118654752f));
            o[j] = cval;
        }
        if (EPI == 2) {
            float4 r0 = *reinterpret_cast<const float4*>(res + base);
            float4 r1 = *reinterpret_cast<const float4*>(res + base + 64);
            o[0]+=r0.x; o[1]+=r0.y; o[2]+=r0.z; o[3]+=r0.w;
            o[4]+=r1.x; o[5]+=r1.y; o[6]+=r1.z; o[7]+=r1.w;
        }
        *reinterpret_cast<float4*>(C + base)      = make_float4(o[0], o[1], o[2], o[3]);
        *reinterpret_cast<float4*>(C + base + 64) = make_float4(o[4], o[5], o[6], o[7]);
    }
}

template <int EPI>
__global__ void __launch_bounds__(256, 2)
gemm_kernel(const float* __restrict__ A, const float* __restrict__ Bm,
            const float* __restrict__ bias, const float* __restrict__ res,
            float* __restrict__ C, int N, int K)
{
    gemm_core<EPI>(A, Bm, bias, res, C, N, K,
                   blockIdx.y * GBM, blockIdx.x * GBN);
}

// fused QKV: grid.z selects weight/bias/output
__global__ void __launch_bounds__(256, 2)
qkv_kernel(const float* __restrict__ xn,
           const float* __restrict__ Wq, const float* __restrict__ Wk,
           const float* __restrict__ Wv,
           const float* __restrict__ bq, const float* __restrict__ bk,
           const float* __restrict__ bv,
           float* __restrict__ q, float* __restrict__ k, float* __restrict__ v)
{
    int z = blockIdx.z;
    const float* W  = (z == 0) ? Wq : (z == 1) ? Wk : Wv;
    const float* bi = (z == 0) ? bq : (z == 1) ? bk : bv;
    float* out      = (z == 0) ? q  : (z == 1) ? k  : v;
    gemm_core<0>(xn, W, bi, nullptr, out, DIM, DIM,
                 blockIdx.y * GBM, blockIdx.x * GBN);
}

// ---------------- RoPE ---------------------------------------------------------
__global__ void rope_kernel(float* __restrict__ q, float* __restrict__ k)
{
    int idx = blockIdx.x * blockDim.x + threadIdx.x;   // over BT*NH*32
    int d  = idx & 31;
    int h  = (idx >> 5) & (NH - 1);
    int bt = idx >> 8;
    int t  = bt & (SEQ - 1);

    float inv_freq = __powf(10000.0f, -(float)(2 * d) / (float)DH);
    float ang = (float)t * inv_freq;
    float c, s;
    sincosf(ang, &s, &c);

    size_t base = (size_t)bt * DIM + h * DH + d;

    float q1 = q[base], q2 = q[base + 32];
    q[base]      = q1 * c - q2 * s;
    q[base + 32] = q2 * c + q1 * s;

    float k1 = k[base], k2 = k[base + 32];
    k[base]      = k1 * c - k2 * s;
    k[base + 32] = k2 * c + k1 * s;
}

// ---------------- Flash-style sliding-window attention ------------------------
#define QT    64
#define KSPAN 320
#define SPAD  324

#define SM_QS   0
#define SM_KV   (64*68)
#define SM_S    (2*64*68)
#define SM_LINV (2*64*68 + 64*SPAD)
#define ATT_SMEM_FLOATS (2*64*68 + 64*SPAD + 64)

__global__ void __launch_bounds__(256)
attn_kernel(const float* __restrict__ q, const float* __restrict__ k,
            const float* __restrict__ v, float* __restrict__ out)
{
    extern __shared__ float sm[];
    float* Qs   = sm + SM_QS;
    float* KV   = sm + SM_KV;
    float* S    = sm + SM_S;
    float* linv = sm + SM_LINV;

    int tid = threadIdx.x;
    int t0  = blockIdx.x * QT;
    int bh  = blockIdx.y;
    int b   = bh >> 3;
    int h   = bh & 7;
    int jbase = t0 - 256;

    int tx = tid & 15, ty = tid >> 4;
    int r0 = ty * 4, c0 = tx * 4;

    #pragma unroll
    for (int s = 0; s < 16; s++) {
        int idx = tid + 256 * s;
        int d = idx & 63, r = idx >> 6;
        Qs[d * 68 + r] = q[(size_t)(b * SEQ + t0 + r) * DIM + h * DH + d] * 0.125f;
    }

    for (int s = 0; s < 5; s++) {
        int kb = jbase + s * 64;
        __syncthreads();
        #pragma unroll
        for (int it = 0; it < 16; it++) {
            int idx = tid + 256 * it;
            int d = idx & 63, c = idx >> 6;
            int j = kb + c;
            int jc = j < 0 ? 0 : j;
            KV[d * 68 + c] = k[(size_t)(b * SEQ + jc) * DIM + h * DH + d];
        }
        __syncthreads();

        float acc[4][4];
        #pragma unroll
        for (int i = 0; i < 4; i++)
            #pragma unroll
            for (int j = 0; j < 4; j++) acc[i][j] = 0.f;

        #pragma unroll 8
        for (int d = 0; d < DH; d++) {
            float4 a4 = *reinterpret_cast<const float4*>(&Qs[d * 68 + r0]);
            float4 b4 = *reinterpret_cast<const float4*>(&KV[d * 68 + c0]);
            float a[4] = {a4.x, a4.y, a4.z, a4.w};
            float bb[4] = {b4.x, b4.y, b4.z, b4.w};
            #pragma unroll
            for (int i = 0; i < 4; i++)
                #pragma unroll
                for (int j = 0; j < 4; j++)
                    acc[i][j] += a[i] * bb[j];
        }

        #pragma unroll
        for (int i = 0; i < 4; i++) {
            int ig = t0 + r0 + i;
            #pragma unroll
            for (int j = 0; j < 4; j++) {
                int jg = kb + c0 + j;
                bool ok = (jg >= 0) && (jg <= ig) && (ig - jg < WIN);
                S[(r0 + i) * SPAD + s * 64 + c0 + j] = ok ? acc[i][j] : -INFINITY;
            }
        }
    }
    __syncthreads();

    {
        int r = tid >> 2, p = tid & 3;
        float m = -INFINITY;
        for (int cc = p; cc < KSPAN; cc += 4) m = fmaxf(m, S[r * SPAD + cc]);
        m = fmaxf(m, __shfl_xor_sync(0xffffffffu, m, 1));
        m = fmaxf(m, __shfl_xor_sync(0xffffffffu, m, 2));
        float sum = 0.f;
        for (int cc = p; cc < KSPAN; cc += 4) {
            float e = __expf(S[r * SPAD + cc] - m);
            S[r * SPAD + cc] = e;
            sum += e;
        }
        sum += __shfl_xor_sync(0xffffffffu, sum, 1);
        sum += __shfl_xor_sync(0xffffffffu, sum, 2);
        if (p == 0) linv[r] = 1.0f / sum;
    }

    float o[4][4];
    #pragma unroll
    for (int i = 0; i < 4; i++)
        #pragma unroll
        for (int j = 0; j < 4; j++) o[i][j] = 0.f;

    for (int s = 0; s < 5; s++) {
        int kb = jbase + s * 64;
        __syncthreads();
        #pragma unroll
        for (int it = 0; it < 16; it++) {
            int idx = tid + 256 * it;
            int c = idx & 63, kk = idx >> 6;
            int j = kb + kk;
            int jc = j < 0 ? 0 : j;
            KV[kk * 68 + c] = v[(size_t)(b * SEQ + jc) * DIM + h * DH + c];
        }
        __syncthreads();

        #pragma unroll 8
        for (int kk = 0; kk < 64; kk++) {
            float4 v4 = *reinterpret_cast<const float4*>(&KV[kk * 68 + c0]);
            float vv[4] = {v4.x, v4.y, v4.z, v4.w};
            float pp[4];
            #pragma unroll
            for (int i = 0; i < 4; i++)
                pp[i] = S[(r0 + i) * SPAD + s * 64 + kk];
            #pragma unroll
            for (int i = 0; i < 4; i++)
                #pragma unroll
                for (int j = 0; j < 4; j++)
                    o[i][j] += pp[i] * vv[j];
        }
    }

    #pragma unroll
    for (int i = 0; i < 4; i++) {
        float li = linv[r0 + i];
        #pragma unroll
        for (int j = 0; j < 4; j++)
            out[(size_t)(b * SEQ + t0 + r0 + i) * DIM + h * DH + c0 + j] = o[i][j] * li;
    }
}

// ---------------- host launcher ----------------------------------------------
extern "C" void kernel_launch(void* const* d_in, const int* in_sizes, int n_in,
                              void* d_out, int out_size)
{
    const float* tokens = (const float*)d_in[0];
    const float* Wq = (const float*)d_in[1];
    const float* Wk = (const float*)d_in[2];
    const float* Wv = (const float*)d_in[3];
    const float* Wo = (const float*)d_in[4];
    const float* bq = (const float*)d_in[5];
    const float* bk = (const float*)d_in[6];
    const float* bv = (const float*)d_in[7];
    const float* bo = (const float*)d_in[8];
    const float* W1 = (const float*)d_in[9];
    const float* b1 = (const float*)d_in[10];
    const float* W2 = (const float*)d_in[11];
    const float* b2 = (const float*)d_in[12];
    const float* g1 = (const float*)d_in[13];
    const float* be1= (const float*)d_in[14];
    const float* g2 = (const float*)d_in[15];
    const float* be2= (const float*)d_in[16];
    const float* gf = (const float*)d_in[17];
    const float* bf = (const float*)d_in[18];

    float *x, *xn, *q, *k, *v, *att, *hb;
    cudaGetSymbolAddress((void**)&x,   g_x);
    cudaGetSymbolAddress((void**)&xn,  g_xn);
    cudaGetSymbolAddress((void**)&q,   g_q);
    cudaGetSymbolAddress((void**)&k,   g_k);
    cudaGetSymbolAddress((void**)&v,   g_v);
    cudaGetSymbolAddress((void**)&att, g_att);
    cudaGetSymbolAddress((void**)&hb,  g_h);

    static const size_t att_smem = ATT_SMEM_FLOATS * sizeof(float);
    cudaFuncSetAttribute(attn_kernel, cudaFuncAttributeMaxDynamicSharedMemorySize,
                         (int)att_smem);

    cudaMemcpyAsync(x, tokens, sizeof(float) * (size_t)BT * DIM,
                    cudaMemcpyDeviceToDevice, 0);

    dim3 gQKV(DIM / GBN, BT / GBM, 3);   // (4, 32, 3)
    dim3 gD  (DIM / GBN, BT / GBM);      // (4, 32)
    dim3 gF  (DFF / GBN, BT / GBM);      // (16, 32)
    dim3 gAtt(SEQ / QT, BATCH * NH);     // (32, 16)

    for (int l = 0; l < NL; l++) {
        const float* Wql = Wq + (size_t)l * DIM * DIM;
        const float* Wkl = Wk + (size_t)l * DIM * DIM;
        const float* Wvl = Wv + (size_t)l * DIM * DIM;
        const float* Wol = Wo + (size_t)l * DIM * DIM;
        const float* W1l = W1 + (size_t)l * DIM * DFF;
        const float* W2l = W2 + (size_t)l * DFF * DIM;

        ln_kernel<<<BT, 256>>>(x, g1 + l * DIM, be1 + l * DIM, xn);

        qkv_kernel<<<gQKV, 256>>>(xn, Wql, Wkl, Wvl,
                                  bq + l * DIM, bk + l * DIM, bv + l * DIM,
                                  q, k, v);

        rope_kernel<<<(BT * NH * 32) / 256, 256>>>(q, k);

        attn_kernel<<<gAtt, 256, att_smem>>>(q, k, v, att);

        gemm_kernel<2><<<gD, 256>>>(att, Wol, bo + l * DIM, x, x, DIM, DIM);

        ln_kernel<<<BT, 256>>>(x, g2 + l * DIM, be2 + l * DIM, xn);

        gemm_kernel<1><<<gF, 256>>>(xn, W1l, b1 + l * DFF, nullptr, hb, DFF, DIM);
        gemm_kernel<2><<<gD, 256>>>(hb, W2l, b2 + l * DIM, x, x, DIM, DFF);
    }

    ln_kernel<<<BT, 256>>>(x, gf, bf, (float*)d_out);
}

// round 5
// speedup vs baseline: 3.2395x; 1.8454x over previous
#include <cuda_runtime.h>
#include <cuda_bf16.h>
#include <math.h>
#include <stdint.h>

#define BATCH 2
#define SEQ   2048
#define DIM   512
#define NH    8
#define DH    64
#define NL    4
#define DFF   2048
#define WIN   256
#define BT    (BATCH*SEQ)   // 4096

// ---------------- scratch (static device globals; no allocation) -------------
__device__ float g_x [BT*DIM];
__device__ float g_q [BT*DIM];
__device__ float g_k [BT*DIM];
__device__ float g_v [BT*DIM];

__device__ __nv_bfloat16 g_xnh [BT*DIM];
__device__ __nv_bfloat16 g_xnl [BT*DIM];
__device__ __nv_bfloat16 g_atth[BT*DIM];
__device__ __nv_bfloat16 g_attl[BT*DIM];
__device__ __nv_bfloat16 g_hbh [BT*DFF];
__device__ __nv_bfloat16 g_hbl [BT*DFF];

// transposed split weights: [L][N][K]
__device__ __nv_bfloat16 g_wqt_h[NL*DIM*DIM],  g_wqt_l[NL*DIM*DIM];
__device__ __nv_bfloat16 g_wkt_h[NL*DIM*DIM],  g_wkt_l[NL*DIM*DIM];
__device__ __nv_bfloat16 g_wvt_h[NL*DIM*DIM],  g_wvt_l[NL*DIM*DIM];
__device__ __nv_bfloat16 g_wot_h[NL*DIM*DIM],  g_wot_l[NL*DIM*DIM];
__device__ __nv_bfloat16 g_w1t_h[NL*DIM*DFF],  g_w1t_l[NL*DIM*DFF];
__device__ __nv_bfloat16 g_w2t_h[NL*DFF*DIM],  g_w2t_l[NL*DFF*DIM];

// ---------------- PTX helpers --------------------------------------------------
__device__ __forceinline__ uint32_t smem_u32(const void* p) {
    uint32_t a;
    asm("{ .reg .u64 t; cvta.to.shared.u64 t, %1; cvt.u32.u64 %0, t; }"
        : "=r"(a) : "l"(p));
    return a;
}

__device__ __forceinline__ void cpa16(uint32_t dst, const void* src)
{
    asm volatile("cp.async.cg.shared.global [%0], [%1], 16;" :: "r"(dst), "l"(src));
}

__device__ __forceinline__ void ldmx4(uint32_t* r, uint32_t addr)
{
    asm volatile("ldmatrix.sync.aligned.m8n8.x4.shared.b16 {%0,%1,%2,%3}, [%4];"
        : "=r"(r[0]), "=r"(r[1]), "=r"(r[2]), "=r"(r[3]) : "r"(addr));
}

__device__ __forceinline__ void mma_bf16(float* c, const uint32_t* a, const uint32_t* b)
{
    asm volatile(
        "mma.sync.aligned.m16n8k16.row.col.f32.bf16.bf16.f32 "
        "{%0,%1,%2,%3}, {%4,%5,%6,%7}, {%8,%9}, {%0,%1,%2,%3};"
        : "+f"(c[0]), "+f"(c[1]), "+f"(c[2]), "+f"(c[3])
        : "r"(a[0]), "r"(a[1]), "r"(a[2]), "r"(a[3]), "r"(b[0]), "r"(b[1]));
}

// ---------------- mma.sync bf16-split GEMM ------------------------------------
// C[M,N] = A[M,K] @ W[K,N]; A as (Ah,Al) [M,K] bf16 row-major; W as (Bh,Bl) [N,K].
#define TKC       32
#define RSTR      40                  // smem row stride in bf16 elems (80 bytes)
#define ARR_BYTES (128*RSTR*2)        // 10240 bytes per 128x32 bf16 array
#define STG_BYTES (4*ARR_BYTES)       // Ah | Al | Bh | Bl = 40960
#define DSM_BYTES (2*STG_BYTES)       // 81920

template <int GELU, int RES, int OUTF32, int OUTBF>
__device__ __forceinline__ void gemm_mm_core(
    const __nv_bfloat16* __restrict__ Ah, const __nv_bfloat16* __restrict__ Al,
    const __nv_bfloat16* __restrict__ Bh, const __nv_bfloat16* __restrict__ Bl,
    const float* __restrict__ bias, const float* __restrict__ res,
    float* __restrict__ C, __nv_bfloat16* __restrict__ Oh, __nv_bfloat16* __restrict__ Ol,
    int N, int K, int m0, int n0)
{
    extern __shared__ char dsm[];
    uint32_t sm0 = smem_u32(dsm);

    int tid  = threadIdx.x;
    int wid  = tid >> 5, lane = tid & 31;
    int mw   = (wid & 3) * 32;     // warp m offset in tile
    int nw   = (wid >> 2) * 64;    // warp n offset in tile

    float acc[2][8][4];
    #pragma unroll
    for (int i = 0; i < 2; i++)
        #pragma unroll
        for (int j = 0; j < 8; j++)
            #pragma unroll
            for (int t = 0; t < 4; t++) acc[i][j][t] = 0.f;

    int nk = K / TKC;

    // stage loader: 2048 16B copies / 256 threads = 8 per thread
    auto load_stage = [&](int c) {
        uint32_t sb = sm0 + (c & 1) * STG_BYTES;
        int k0 = c * TKC;
        #pragma unroll
        for (int it = 0; it < 8; it++) {
            int idx  = it * 256 + tid;       // 0..2047
            int arr  = idx >> 9;             // 0..3
            int rem  = idx & 511;
            int row  = rem >> 2;
            int part = rem & 3;
            uint32_t dst = sb + arr * ARR_BYTES + row * (RSTR * 2) + part * 16;
            const __nv_bfloat16* src;
            if      (arr == 0) src = Ah + (size_t)(m0 + row) * K + k0 + part * 8;
            else if (arr == 1) src = Al + (size_t)(m0 + row) * K + k0 + part * 8;
            else if (arr == 2) src = Bh + (size_t)(n0 + row) * K + k0 + part * 8;
            else               src = Bl + (size_t)(n0 + row) * K + k0 + part * 8;
            cpa16(dst, src);
        }
        asm volatile("cp.async.commit_group;" ::: "memory");
    };

    load_stage(0);

    // per-thread ldmatrix address offsets (element units within an array)
    int a_row = mw + (lane & 15);
    int a_koff = (lane >> 4) * 8;
    int b_row = nw + (lane & 7) + ((lane >> 4) & 1) * 8;
    int b_koff = ((lane >> 3) & 1) * 8;

    for (int c = 0; c < nk; c++) {
        asm volatile("cp.async.wait_group 0;" ::: "memory");
        __syncthreads();

        if (c + 1 < nk) load_stage(c + 1);

        uint32_t sb  = sm0 + (c & 1) * STG_BYTES;
        uint32_t sah = sb;
        uint32_t sal = sb + ARR_BYTES;
        uint32_t sbh = sb + 2 * ARR_BYTES;
        uint32_t sbl = sb + 3 * ARR_BYTES;

        #pragma unroll
        for (int h = 0; h < 2; h++) {            // two k16 halves of the chunk
            int k0 = h * 16;
            uint32_t ah[2][4], al[2][4];
            #pragma unroll
            for (int mt = 0; mt < 2; mt++) {
                uint32_t off = ((a_row + mt * 16) * RSTR + k0 + a_koff) * 2;
                ldmx4(ah[mt], sah + off);
                ldmx4(al[mt], sal + off);
            }
            #pragma unroll
            for (int ng = 0; ng < 4; ng++) {     // pairs of n-tiles
                uint32_t bh[4], bl[4];
                uint32_t off = ((b_row + ng * 16) * RSTR + k0 + b_koff) * 2;
                ldmx4(bh, sbh + off);
                ldmx4(bl, sbl + off);
                #pragma unroll
                for (int mt = 0; mt < 2; mt++) {
                    mma_bf16(acc[mt][2*ng],   ah[mt], bh);
                    mma_bf16(acc[mt][2*ng],   ah[mt], bl);
                    mma_bf16(acc[mt][2*ng],   al[mt], bh);
                    mma_bf16(acc[mt][2*ng+1], ah[mt], bh + 2);
                    mma_bf16(acc[mt][2*ng+1], ah[mt], bl + 2);
                    mma_bf16(acc[mt][2*ng+1], al[mt], bh + 2);
                }
            }
        }
        __syncthreads();
    }

    // ---- epilogue ----
    int cbase_n = n0 + nw + (lane & 3) * 2;
    #pragma unroll
    for (int mt = 0; mt < 2; mt++) {
        #pragma unroll
        for (int half = 0; half < 2; half++) {
            int row = m0 + mw + mt * 16 + (lane >> 2) + half * 8;
            size_t rbase = (size_t)row * N;
            #pragma unroll
            for (int nt = 0; nt < 8; nt++) {
                int col = cbase_n + nt * 8;
                float v0 = acc[mt][nt][half * 2 + 0];
                float v1 = acc[mt][nt][half * 2 + 1];
                float2 b2 = *reinterpret_cast<const float2*>(bias + col);
                v0 += b2.x; v1 += b2.y;
                if (GELU) {
                    v0 = 0.5f * v0 * (1.0f + erff(v0 * 0.70710678118654752f));
                    v1 = 0.5f * v1 * (1.0f + erff(v1 * 0.70710678118654752f));
                }
                if (RES) {
                    float2 r2 = *reinterpret_cast<const float2*>(res + rbase + col);
                    v0 += r2.x; v1 += r2.y;
                }
                if (OUTF32) {
                    *reinterpret_cast<float2*>(C + rbase + col) = make_float2(v0, v1);
                }
                if (OUTBF) {
                    __nv_bfloat16 h0 = __float2bfloat16(v0);
                    __nv_bfloat16 h1 = __float2bfloat16(v1);
                    __nv_bfloat162 hh; hh.x = h0; hh.y = h1;
                    __nv_bfloat162 ll;
                    ll.x = __float2bfloat16(v0 - __bfloat162float(h0));
                    ll.y = __float2bfloat16(v1 - __bfloat162float(h1));
                    *reinterpret_cast<__nv_bfloat162*>(Oh + rbase + col) = hh;
                    *reinterpret_cast<__nv_bfloat162*>(Ol + rbase + col) = ll;
                }
            }
        }
    }
}

template <int GELU, int RES, int OUTF32, int OUTBF>
__global__ void __launch_bounds__(256, 1)
gemm_mm(const __nv_bfloat16* __restrict__ Ah, const __nv_bfloat16* __restrict__ Al,
        const __nv_bfloat16* __restrict__ Bh, const __nv_bfloat16* __restrict__ Bl,
        const float* __restrict__ bias, const float* __restrict__ res,
        float* __restrict__ C, __nv_bfloat16* __restrict__ Oh,
        __nv_bfloat16* __restrict__ Ol, int N, int K)
{
    gemm_mm_core<GELU, RES, OUTF32, OUTBF>(Ah, Al, Bh, Bl, bias, res, C, Oh, Ol,
                                           N, K, blockIdx.y * 128, blockIdx.x * 128);
}

// fused QKV
__global__ void __launch_bounds__(256, 1)
qkv_mm(const __nv_bfloat16* __restrict__ Ah, const __nv_bfloat16* __restrict__ Al,
       const __nv_bfloat16* __restrict__ Bqh, const __nv_bfloat16* __restrict__ Bql,
       const __nv_bfloat16* __restrict__ Bkh, const __nv_bfloat16* __restrict__ Bkl,
       const __nv_bfloat16* __restrict__ Bvh, const __nv_bfloat16* __restrict__ Bvl,
       const float* __restrict__ bq, const float* __restrict__ bk,
       const float* __restrict__ bv,
       float* __restrict__ q, float* __restrict__ k, float* __restrict__ v)
{
    int z = blockIdx.z;
    const __nv_bfloat16* Bh = (z == 0) ? Bqh : (z == 1) ? Bkh : Bvh;
    const __nv_bfloat16* Bl = (z == 0) ? Bql : (z == 1) ? Bkl : Bvl;
    const float* bi = (z == 0) ? bq : (z == 1) ? bk : bv;
    float* C        = (z == 0) ? q  : (z == 1) ? k  : v;
    gemm_mm_core<0, 0, 1, 0>(Ah, Al, Bh, Bl, bi, nullptr, C, nullptr, nullptr,
                             DIM, DIM, blockIdx.y * 128, blockIdx.x * 128);
}

// ---------------- weight transpose + bf16 split -------------------------------
__global__ void wconv_kernel(const float* __restrict__ W,
                             __nv_bfloat16* __restrict__ hiT,
                             __nv_bfloat16* __restrict__ loT, int K, int N)
{
    __shared__ float t[32][33];
    int n0 = blockIdx.x * 32, k0 = blockIdx.y * 32;
    size_t lofs = (size_t)blockIdx.z * K * N;
    const float* Wl = W + lofs;
    int tx = threadIdx.x, ty = threadIdx.y;
    #pragma unroll
    for (int i = 0; i < 4; i++)
        t[ty + 8 * i][tx] = Wl[(size_t)(k0 + ty + 8 * i) * N + n0 + tx];
    __syncthreads();
    __nv_bfloat16* ho = hiT + lofs;
    __nv_bfloat16* lo = loT + lofs;
    #pragma unroll
    for (int i = 0; i < 4; i++) {
        float v = t[tx][ty + 8 * i];
        __nv_bfloat16 h = __float2bfloat16(v);
        float r = v - __bfloat162float(h);
        ho[(size_t)(n0 + ty + 8 * i) * K + k0 + tx] = h;
        lo[(size_t)(n0 + ty + 8 * i) * K + k0 + tx] = __float2bfloat16(r);
    }
}

// ---------------- LayerNorm ----------------------------------------------------
__global__ void ln_kernel(const float* __restrict__ x, const float* __restrict__ g,
                          const float* __restrict__ b, float* __restrict__ y,
                          __nv_bfloat16* __restrict__ yh, __nv_bfloat16* __restrict__ yl)
{
    int row = blockIdx.x;
    int tid = threadIdx.x;
    const float* xr = x + (size_t)row * DIM;

    float v0 = xr[tid];
    float v1 = xr[tid + 256];
    float s  = v0 + v1;
    float ss = v0 * v0 + v1 * v1;
    #pragma unroll
    for (int o = 16; o; o >>= 1) {
        s  += __shfl_xor_sync(0xffffffffu, s,  o);
        ss += __shfl_xor_sync(0xffffffffu, ss, o);
    }
    __shared__ float ws[8], wss[8];
    int w = tid >> 5, ln = tid & 31;
    if (ln == 0) { ws[w] = s; wss[w] = ss; }
    __syncthreads();
    __shared__ float s_mu, s_rstd;
    if (tid == 0) {
        float S = 0.f, SS = 0.f;
        #pragma unroll
        for (int i = 0; i < 8; i++) { S += ws[i]; SS += wss[i]; }
        float mu  = S * (1.0f / DIM);
        float var = SS * (1.0f / DIM) - mu * mu;
        s_mu = mu; s_rstd = rsqrtf(var + 1e-5f);
    }
    __syncthreads();
    float mu = s_mu, rstd = s_rstd;
    float o0 = (v0 - mu) * rstd * g[tid]       + b[tid];
    float o1 = (v1 - mu) * rstd * g[tid + 256] + b[tid + 256];
    size_t base = (size_t)row * DIM;
    if (y) {
        y[base + tid]       = o0;
        y[base + tid + 256] = o1;
    }
    if (yh) {
        __nv_bfloat16 h0 = __float2bfloat16(o0);
        __nv_bfloat16 h1 = __float2bfloat16(o1);
        yh[base + tid]       = h0;
        yh[base + tid + 256] = h1;
        yl[base + tid]       = __float2bfloat16(o0 - __bfloat162float(h0));
        yl[base + tid + 256] = __float2bfloat16(o1 - __bfloat162float(h1));
    }
}

// ---------------- RoPE ---------------------------------------------------------
__global__ void rope_kernel(float* __restrict__ q, float* __restrict__ k)
{
    int idx = blockIdx.x * blockDim.x + threadIdx.x;
    int d  = idx & 31;
    int h  = (idx >> 5) & (NH - 1);
    int bt = idx >> 8;
    int t  = bt & (SEQ - 1);

    float inv_freq = __powf(10000.0f, -(float)(2 * d) / (float)DH);
    float ang = (float)t * inv_freq;
    float c, s;
    sincosf(ang, &s, &c);

    size_t base = (size_t)bt * DIM + h * DH + d;

    float q1 = q[base], q2 = q[base + 32];
    q[base]      = q1 * c - q2 * s;
    q[base + 32] = q2 * c + q1 * s;

    float k1 = k[base], k2 = k[base + 32];
    k[base]      = k1 * c - k2 * s;
    k[base + 32] = k2 * c + k1 * s;
}

// ---------------- Flash-style sliding-window attention ------------------------
#define QT    64
#define KSPAN 320
#define SPAD  324

#define SM_QS   0
#define SM_KV   (64*68)
#define SM_S    (2*64*68)
#define SM_LINV (2*64*68 + 64*SPAD)
#define ATT_SMEM_FLOATS (2*64*68 + 64*SPAD + 64)

__global__ void __launch_bounds__(256)
attn_kernel(const float* __restrict__ q, const float* __restrict__ k,
            const float* __restrict__ v,
            __nv_bfloat16* __restrict__ oh, __nv_bfloat16* __restrict__ ol)
{
    extern __shared__ float sm[];
    float* Qs   = sm + SM_QS;
    float* KV   = sm + SM_KV;
    float* S    = sm + SM_S;
    float* linv = sm + SM_LINV;

    int tid = threadIdx.x;
    int t0  = blockIdx.x * QT;
    int bh  = blockIdx.y;
    int b   = bh >> 3;
    int h   = bh & 7;
    int jbase = t0 - 256;

    int tx = tid & 15, ty = tid >> 4;
    int r0 = ty * 4, c0 = tx * 4;

    #pragma unroll
    for (int s = 0; s < 16; s++) {
        int idx = tid + 256 * s;
        int d = idx & 63, r = idx >> 6;
        Qs[d * 68 + r] = q[(size_t)(b * SEQ + t0 + r) * DIM + h * DH + d] * 0.125f;
    }

    for (int s = 0; s < 5; s++) {
        int kb = jbase + s * 64;
        __syncthreads();
        #pragma unroll
        for (int it = 0; it < 16; it++) {
            int idx = tid + 256 * it;
            int d = idx & 63, c = idx >> 6;
            int j = kb + c;
            int jc = j < 0 ? 0 : j;
            KV[d * 68 + c] = k[(size_t)(b * SEQ + jc) * DIM + h * DH + d];
        }
        __syncthreads();

        float acc[4][4];
        #pragma unroll
        for (int i = 0; i < 4; i++)
            #pragma unroll
            for (int j = 0; j < 4; j++) acc[i][j] = 0.f;

        #pragma unroll 8
        for (int d = 0; d < DH; d++) {
            float4 a4 = *reinterpret_cast<const float4*>(&Qs[d * 68 + r0]);
            float4 b4 = *reinterpret_cast<const float4*>(&KV[d * 68 + c0]);
            float a[4] = {a4.x, a4.y, a4.z, a4.w};
            float bb[4] = {b4.x, b4.y, b4.z, b4.w};
            #pragma unroll
            for (int i = 0; i < 4; i++)
                #pragma unroll
                for (int j = 0; j < 4; j++)
                    acc[i][j] += a[i] * bb[j];
        }

        #pragma unroll
        for (int i = 0; i < 4; i++) {
            int ig = t0 + r0 + i;
            #pragma unroll
            for (int j = 0; j < 4; j++) {
                int jg = kb + c0 + j;
                bool ok = (jg >= 0) && (jg <= ig) && (ig - jg < WIN);
                S[(r0 + i) * SPAD + s * 64 + c0 + j] = ok ? acc[i][j] : -INFINITY;
            }
        }
    }
    __syncthreads();

    {
        int r = tid >> 2, p = tid & 3;
        float m = -INFINITY;
        for (int cc = p; cc < KSPAN; cc += 4) m = fmaxf(m, S[r * SPAD + cc]);
        m = fmaxf(m, __shfl_xor_sync(0xffffffffu, m, 1));
        m = fmaxf(m, __shfl_xor_sync(0xffffffffu, m, 2));
        float sum = 0.f;
        for (int cc = p; cc < KSPAN; cc += 4) {
            float e = __expf(S[r * SPAD + cc] - m);
            S[r * SPAD + cc] = e;
            sum += e;
        }
        sum += __shfl_xor_sync(0xffffffffu, sum, 1);
        sum += __shfl_xor_sync(0xffffffffu, sum, 2);
        if (p == 0) linv[r] = 1.0f / sum;
    }

    float o[4][4];
    #pragma unroll
    for (int i = 0; i < 4; i++)
        #pragma unroll
        for (int j = 0; j < 4; j++) o[i][j] = 0.f;

    for (int s = 0; s < 5; s++) {
        int kb = jbase + s * 64;
        __syncthreads();
        #pragma unroll
        for (int it = 0; it < 16; it++) {
            int idx = tid + 256 * it;
            int c = idx & 63, kk = idx >> 6;
            int j = kb + kk;
            int jc = j < 0 ? 0 : j;
            KV[kk * 68 + c] = v[(size_t)(b * SEQ + jc) * DIM + h * DH + c];
        }
        __syncthreads();

        #pragma unroll 8
        for (int kk = 0; kk < 64; kk++) {
            float4 v4 = *reinterpret_cast<const float4*>(&KV[kk * 68 + c0]);
            float vv[4] = {v4.x, v4.y, v4.z, v4.w};
            float pp[4];
            #pragma unroll
            for (int i = 0; i < 4; i++)
                pp[i] = S[(r0 + i) * SPAD + s * 64 + kk];
            #pragma unroll
            for (int i = 0; i < 4; i++)
                #pragma unroll
                for (int j = 0; j < 4; j++)
                    o[i][j] += pp[i] * vv[j];
        }
    }

    #pragma unroll
    for (int i = 0; i < 4; i++) {
        float li = linv[r0 + i];
        size_t base = (size_t)(b * SEQ + t0 + r0 + i) * DIM + h * DH + c0;
        #pragma unroll
        for (int j = 0; j < 4; j++) {
            float val = o[i][j] * li;
            __nv_bfloat16 hh = __float2bfloat16(val);
            oh[base + j] = hh;
            ol[base + j] = __float2bfloat16(val - __bfloat162float(hh));
        }
    }
}

// ---------------- host launcher ----------------------------------------------
extern "C" void kernel_launch(void* const* d_in, const int* in_sizes, int n_in,
                              void* d_out, int out_size)
{
    const float* tokens = (const float*)d_in[0];
    const float* Wq = (const float*)d_in[1];
    const float* Wk = (const float*)d_in[2];
    const float* Wv = (const float*)d_in[3];
    const float* Wo = (const float*)d_in[4];
    const float* bq = (const float*)d_in[5];
    const float* bk = (const float*)d_in[6];
    const float* bv = (const float*)d_in[7];
    const float* bo = (const float*)d_in[8];
    const float* W1 = (const float*)d_in[9];
    const float* b1 = (const float*)d_in[10];
    const float* W2 = (const float*)d_in[11];
    const float* b2 = (const float*)d_in[12];
    const float* g1 = (const float*)d_in[13];
    const float* be1= (const float*)d_in[14];
    const float* g2 = (const float*)d_in[15];
    const float* be2= (const float*)d_in[16];
    const float* gf = (const float*)d_in[17];
    const float* bf = (const float*)d_in[18];

    float *x, *q, *k, *v;
    cudaGetSymbolAddress((void**)&x, g_x);
    cudaGetSymbolAddress((void**)&q, g_q);
    cudaGetSymbolAddress((void**)&k, g_k);
    cudaGetSymbolAddress((void**)&v, g_v);

    __nv_bfloat16 *xnh, *xnl, *atth, *attl, *hbh, *hbl;
    cudaGetSymbolAddress((void**)&xnh,  g_xnh);
    cudaGetSymbolAddress((void**)&xnl,  g_xnl);
    cudaGetSymbolAddress((void**)&atth, g_atth);
    cudaGetSymbolAddress((void**)&attl, g_attl);
    cudaGetSymbolAddress((void**)&hbh,  g_hbh);
    cudaGetSymbolAddress((void**)&hbl,  g_hbl);

    __nv_bfloat16 *wqh,*wql,*wkh,*wkl,*wvh,*wvl,*woh,*wol,*w1h,*w1l,*w2h,*w2l;
    cudaGetSymbolAddress((void**)&wqh, g_wqt_h); cudaGetSymbolAddress((void**)&wql, g_wqt_l);
    cudaGetSymbolAddress((void**)&wkh, g_wkt_h); cudaGetSymbolAddress((void**)&wkl, g_wkt_l);
    cudaGetSymbolAddress((void**)&wvh, g_wvt_h); cudaGetSymbolAddress((void**)&wvl, g_wvt_l);
    cudaGetSymbolAddress((void**)&woh, g_wot_h); cudaGetSymbolAddress((void**)&wol, g_wot_l);
    cudaGetSymbolAddress((void**)&w1h, g_w1t_h); cudaGetSymbolAddress((void**)&w1l, g_w1t_l);
    cudaGetSymbolAddress((void**)&w2h, g_w2t_h); cudaGetSymbolAddress((void**)&w2l, g_w2t_l);

    static const size_t att_smem = ATT_SMEM_FLOATS * sizeof(float);
    cudaFuncSetAttribute(attn_kernel, cudaFuncAttributeMaxDynamicSharedMemorySize,
                         (int)att_smem);
    cudaFuncSetAttribute(qkv_mm, cudaFuncAttributeMaxDynamicSharedMemorySize, DSM_BYTES);
    cudaFuncSetAttribute(gemm_mm<0,1,1,0>, cudaFuncAttributeMaxDynamicSharedMemorySize, DSM_BYTES);
    cudaFuncSetAttribute(gemm_mm<1,0,0,1>, cudaFuncAttributeMaxDynamicSharedMemorySize, DSM_BYTES);

    cudaMemcpyAsync(x, tokens, sizeof(float) * (size_t)BT * DIM,
                    cudaMemcpyDeviceToDevice, 0);

    // weight conversion (all layers)
    {
        dim3 blk(32, 8);
        dim3 gdd(DIM / 32, DIM / 32, NL);
        wconv_kernel<<<gdd, blk>>>(Wq, wqh, wql, DIM, DIM);
        wconv_kernel<<<gdd, blk>>>(Wk, wkh, wkl, DIM, DIM);
        wconv_kernel<<<gdd, blk>>>(Wv, wvh, wvl, DIM, DIM);
        wconv_kernel<<<gdd, blk>>>(Wo, woh, wol, DIM, DIM);
        dim3 g1d(DFF / 32, DIM / 32, NL);
        wconv_kernel<<<g1d, blk>>>(W1, w1h, w1l, DIM, DFF);
        dim3 g2d(DIM / 32, DFF / 32, NL);
        wconv_kernel<<<g2d, blk>>>(W2, w2h, w2l, DFF, DIM);
    }

    dim3 gQKV(DIM / 128, BT / 128, 3);   // (4, 32, 3)
    dim3 gD  (DIM / 128, BT / 128);      // (4, 32)
    dim3 gF  (DFF / 128, BT / 128);      // (16, 32)
    dim3 gAtt(SEQ / QT, BATCH * NH);     // (32, 16)

    for (int l = 0; l < NL; l++) {
        size_t wofs  = (size_t)l * DIM * DIM;
        size_t w1ofs = (size_t)l * DIM * DFF;

        ln_kernel<<<BT, 256>>>(x, g1 + l * DIM, be1 + l * DIM, nullptr, xnh, xnl);

        qkv_mm<<<gQKV, 256, DSM_BYTES>>>(xnh, xnl,
                                         wqh + wofs, wql + wofs,
                                         wkh + wofs, wkl + wofs,
                                         wvh + wofs, wvl + wofs,
                                         bq + l * DIM, bk + l * DIM, bv + l * DIM,
                                         q, k, v);

        rope_kernel<<<(BT * NH * 32) / 256, 256>>>(q, k);

        attn_kernel<<<gAtt, 256, att_smem>>>(q, k, v, atth, attl);

        gemm_mm<0,1,1,0><<<gD, 256, DSM_BYTES>>>(atth, attl, woh + wofs, wol + wofs,
                                                 bo + l * DIM, x, x, nullptr, nullptr,
                                                 DIM, DIM);

        ln_kernel<<<BT, 256>>>(x, g2 + l * DIM, be2 + l * DIM, nullptr, xnh, xnl);

        gemm_mm<1,0,0,1><<<gF, 256, DSM_BYTES>>>(xnh, xnl, w1h + w1ofs, w1l + w1ofs,
                                                 b1 + l * DFF, nullptr, nullptr, hbh, hbl,
                                                 DFF, DIM);

        gemm_mm<0,1,1,0><<<gD, 256, DSM_BYTES>>>(hbh, hbl, w2h + w1ofs, w2l + w1ofs,
                                                 b2 + l * DIM, x, x, nullptr, nullptr,
                                                 DIM, DFF);
    }

    ln_kernel<<<BT, 256>>>(x, gf, bf, (float*)d_out, nullptr, nullptr);
}

// round 6
// speedup vs baseline: 3.5333x; 1.0907x over previous
#include <cuda_runtime.h>
#include <cuda_bf16.h>
#include <math.h>
#include <stdint.h>

#define BATCH 2
#define SEQ   2048
#define DIM   512
#define NH    8
#define DH    64
#define NL    4
#define DFF   2048
#define WIN   256
#define BT    (BATCH*SEQ)   // 4096

// ---------------- scratch (static device globals; no allocation) -------------
__device__ float g_x [BT*DIM];
__device__ float g_q [BT*DIM];
__device__ float g_k [BT*DIM];
__device__ float g_v [BT*DIM];

__device__ __nv_bfloat16 g_xnh [BT*DIM];
__device__ __nv_bfloat16 g_xnl [BT*DIM];
__device__ __nv_bfloat16 g_atth[BT*DIM];
__device__ __nv_bfloat16 g_attl[BT*DIM];
__device__ __nv_bfloat16 g_hbh [BT*DFF];
__device__ __nv_bfloat16 g_hbl [BT*DFF];

// transposed split weights: [L][N][K]
__device__ __nv_bfloat16 g_wqt_h[NL*DIM*DIM],  g_wqt_l[NL*DIM*DIM];
__device__ __nv_bfloat16 g_wkt_h[NL*DIM*DIM],  g_wkt_l[NL*DIM*DIM];
__device__ __nv_bfloat16 g_wvt_h[NL*DIM*DIM],  g_wvt_l[NL*DIM*DIM];
__device__ __nv_bfloat16 g_wot_h[NL*DIM*DIM],  g_wot_l[NL*DIM*DIM];
__device__ __nv_bfloat16 g_w1t_h[NL*DIM*DFF],  g_w1t_l[NL*DIM*DFF];
__device__ __nv_bfloat16 g_w2t_h[NL*DFF*DIM],  g_w2t_l[NL*DFF*DIM];

// ---------------- PTX helpers --------------------------------------------------
__device__ __forceinline__ uint32_t smem_u32(const void* p) {
    uint32_t a;
    asm("{ .reg .u64 t; cvta.to.shared.u64 t, %1; cvt.u32.u64 %0, t; }"
        : "=r"(a) : "l"(p));
    return a;
}

__device__ __forceinline__ void cpa16(uint32_t dst, const void* src)
{
    asm volatile("cp.async.cg.shared.global [%0], [%1], 16;" :: "r"(dst), "l"(src));
}

__device__ __forceinline__ void ldmx4(uint32_t* r, uint32_t addr)
{
    asm volatile("ldmatrix.sync.aligned.m8n8.x4.shared.b16 {%0,%1,%2,%3}, [%4];"
        : "=r"(r[0]), "=r"(r[1]), "=r"(r[2]), "=r"(r[3]) : "r"(addr));
}

__device__ __forceinline__ void mma_bf16(float* c, const uint32_t* a, const uint32_t* b)
{
    asm volatile(
        "mma.sync.aligned.m16n8k16.row.col.f32.bf16.bf16.f32 "
        "{%0,%1,%2,%3}, {%4,%5,%6,%7}, {%8,%9}, {%0,%1,%2,%3};"
        : "+f"(c[0]), "+f"(c[1]), "+f"(c[2]), "+f"(c[3])
        : "r"(a[0]), "r"(a[1]), "r"(a[2]), "r"(a[3]), "r"(b[0]), "r"(b[1]));
}

__device__ __forceinline__ void split_bf16(float v, __nv_bfloat16& h, __nv_bfloat16& l)
{
    h = __float2bfloat16(v);
    l = __float2bfloat16(v - __bfloat162float(h));
}

// ---------------- mma.sync bf16-split GEMM ------------------------------------
#define TKC       32
#define RSTR      40                  // smem row stride in bf16 elems (80 bytes)
#define ARR_BYTES (128*RSTR*2)
#define STG_BYTES (4*ARR_BYTES)
#define DSM_BYTES (2*STG_BYTES)

template <int GELU, int RES, int OUTF32, int OUTBF>
__device__ __forceinline__ void gemm_mm_core(
    const __nv_bfloat16* __restrict__ Ah, const __nv_bfloat16* __restrict__ Al,
    const __nv_bfloat16* __restrict__ Bh, const __nv_bfloat16* __restrict__ Bl,
    const float* __restrict__ bias, const float* __restrict__ res,
    float* __restrict__ C, __nv_bfloat16* __restrict__ Oh, __nv_bfloat16* __restrict__ Ol,
    int N, int K, int m0, int n0)
{
    extern __shared__ char dsm[];
    uint32_t sm0 = smem_u32(dsm);

    int tid  = threadIdx.x;
    int wid  = tid >> 5, lane = tid & 31;
    int mw   = (wid & 3) * 32;
    int nw   = (wid >> 2) * 64;

    float acc[2][8][4];
    #pragma unroll
    for (int i = 0; i < 2; i++)
        #pragma unroll
        for (int j = 0; j < 8; j++)
            #pragma unroll
            for (int t = 0; t < 4; t++) acc[i][j][t] = 0.f;

    int nk = K / TKC;

    auto load_stage = [&](int c) {
        uint32_t sb = sm0 + (c & 1) * STG_BYTES;
        int k0 = c * TKC;
        #pragma unroll
        for (int it = 0; it < 8; it++) {
            int idx  = it * 256 + tid;
            int arr  = idx >> 9;
            int rem  = idx & 511;
            int row  = rem >> 2;
            int part = rem & 3;
            uint32_t dst = sb + arr * ARR_BYTES + row * (RSTR * 2) + part * 16;
            const __nv_bfloat16* src;
            if      (arr == 0) src = Ah + (size_t)(m0 + row) * K + k0 + part * 8;
            else if (arr == 1) src = Al + (size_t)(m0 + row) * K + k0 + part * 8;
            else if (arr == 2) src = Bh + (size_t)(n0 + row) * K + k0 + part * 8;
            else               src = Bl + (size_t)(n0 + row) * K + k0 + part * 8;
            cpa16(dst, src);
        }
        asm volatile("cp.async.commit_group;" ::: "memory");
    };

    load_stage(0);

    int a_row = mw + (lane & 15);
    int a_koff = (lane >> 4) * 8;
    int b_row = nw + (lane & 7) + ((lane >> 4) & 1) * 8;
    int b_koff = ((lane >> 3) & 1) * 8;

    for (int c = 0; c < nk; c++) {
        asm volatile("cp.async.wait_group 0;" ::: "memory");
        __syncthreads();

        if (c + 1 < nk) load_stage(c + 1);

        uint32_t sb  = sm0 + (c & 1) * STG_BYTES;
        uint32_t sah = sb;
        uint32_t sal = sb + ARR_BYTES;
        uint32_t sbh = sb + 2 * ARR_BYTES;
        uint32_t sbl = sb + 3 * ARR_BYTES;

        #pragma unroll
        for (int h = 0; h < 2; h++) {
            int k0 = h * 16;
            uint32_t ah[2][4], al[2][4];
            #pragma unroll
            for (int mt = 0; mt < 2; mt++) {
                uint32_t off = ((a_row + mt * 16) * RSTR + k0 + a_koff) * 2;
                ldmx4(ah[mt], sah + off);
                ldmx4(al[mt], sal + off);
            }
            #pragma unroll
            for (int ng = 0; ng < 4; ng++) {
                uint32_t bh[4], bl[4];
                uint32_t off = ((b_row + ng * 16) * RSTR + k0 + b_koff) * 2;
                ldmx4(bh, sbh + off);
                ldmx4(bl, sbl + off);
                #pragma unroll
                for (int mt = 0; mt < 2; mt++) {
                    mma_bf16(acc[mt][2*ng],   ah[mt], bh);
                    mma_bf16(acc[mt][2*ng],   ah[mt], bl);
                    mma_bf16(acc[mt][2*ng],   al[mt], bh);
                    mma_bf16(acc[mt][2*ng+1], ah[mt], bh + 2);
                    mma_bf16(acc[mt][2*ng+1], ah[mt], bl + 2);
                    mma_bf16(acc[mt][2*ng+1], al[mt], bh + 2);
                }
            }
        }
        __syncthreads();
    }

    int cbase_n = n0 + nw + (lane & 3) * 2;
    #pragma unroll
    for (int mt = 0; mt < 2; mt++) {
        #pragma unroll
        for (int half = 0; half < 2; half++) {
            int row = m0 + mw + mt * 16 + (lane >> 2) + half * 8;
            size_t rbase = (size_t)row * N;
            #pragma unroll
            for (int nt = 0; nt < 8; nt++) {
                int col = cbase_n + nt * 8;
                float v0 = acc[mt][nt][half * 2 + 0];
                float v1 = acc[mt][nt][half * 2 + 1];
                float2 b2 = *reinterpret_cast<const float2*>(bias + col);
                v0 += b2.x; v1 += b2.y;
                if (GELU) {
                    v0 = 0.5f * v0 * (1.0f + erff(v0 * 0.70710678118654752f));
                    v1 = 0.5f * v1 * (1.0f + erff(v1 * 0.70710678118654752f));
                }
                if (RES) {
                    float2 r2 = *reinterpret_cast<const float2*>(res + rbase + col);
                    v0 += r2.x; v1 += r2.y;
                }
                if (OUTF32) {
                    *reinterpret_cast<float2*>(C + rbase + col) = make_float2(v0, v1);
                }
                if (OUTBF) {
                    __nv_bfloat16 h0, l0, h1, l1;
                    split_bf16(v0, h0, l0);
                    split_bf16(v1, h1, l1);
                    __nv_bfloat162 hh; hh.x = h0; hh.y = h1;
                    __nv_bfloat162 ll; ll.x = l0; ll.y = l1;
                    *reinterpret_cast<__nv_bfloat162*>(Oh + rbase + col) = hh;
                    *reinterpret_cast<__nv_bfloat162*>(Ol + rbase + col) = ll;
                }
            }
        }
    }
}

template <int GELU, int RES, int OUTF32, int OUTBF>
__global__ void __launch_bounds__(256, 1)
gemm_mm(const __nv_bfloat16* __restrict__ Ah, const __nv_bfloat16* __restrict__ Al,
        const __nv_bfloat16* __restrict__ Bh, const __nv_bfloat16* __restrict__ Bl,
        const float* __restrict__ bias, const float* __restrict__ res,
        float* __restrict__ C, __nv_bfloat16* __restrict__ Oh,
        __nv_bfloat16* __restrict__ Ol, int N, int K)
{
    gemm_mm_core<GELU, RES, OUTF32, OUTBF>(Ah, Al, Bh, Bl, bias, res, C, Oh, Ol,
                                           N, K, blockIdx.y * 128, blockIdx.x * 128);
}

__global__ void __launch_bounds__(256, 1)
qkv_mm(const __nv_bfloat16* __restrict__ Ah, const __nv_bfloat16* __restrict__ Al,
       const __nv_bfloat16* __restrict__ Bqh, const __nv_bfloat16* __restrict__ Bql,
       const __nv_bfloat16* __restrict__ Bkh, const __nv_bfloat16* __restrict__ Bkl,
       const __nv_bfloat16* __restrict__ Bvh, const __nv_bfloat16* __restrict__ Bvl,
       const float* __restrict__ bq, const float* __restrict__ bk,
       const float* __restrict__ bv,
       float* __restrict__ q, float* __restrict__ k, float* __restrict__ v)
{
    int z = blockIdx.z;
    const __nv_bfloat16* Bh = (z == 0) ? Bqh : (z == 1) ? Bkh : Bvh;
    const __nv_bfloat16* Bl = (z == 0) ? Bql : (z == 1) ? Bkl : Bvl;
    const float* bi = (z == 0) ? bq : (z == 1) ? bk : bv;
    float* C        = (z == 0) ? q  : (z == 1) ? k  : v;
    gemm_mm_core<0, 0, 1, 0>(Ah, Al, Bh, Bl, bi, nullptr, C, nullptr, nullptr,
                             DIM, DIM, blockIdx.y * 128, blockIdx.x * 128);
}

// ---------------- weight transpose + bf16 split -------------------------------
__global__ void wconv_kernel(const float* __restrict__ W,
                             __nv_bfloat16* __restrict__ hiT,
                             __nv_bfloat16* __restrict__ loT, int K, int N)
{
    __shared__ float t[32][33];
    int n0 = blockIdx.x * 32, k0 = blockIdx.y * 32;
    size_t lofs = (size_t)blockIdx.z * K * N;
    const float* Wl = W + lofs;
    int tx = threadIdx.x, ty = threadIdx.y;
    #pragma unroll
    for (int i = 0; i < 4; i++)
        t[ty + 8 * i][tx] = Wl[(size_t)(k0 + ty + 8 * i) * N + n0 + tx];
    __syncthreads();
    __nv_bfloat16* ho = hiT + lofs;
    __nv_bfloat16* lo = loT + lofs;
    #pragma unroll
    for (int i = 0; i < 4; i++) {
        float v = t[tx][ty + 8 * i];
        __nv_bfloat16 h, l;
        split_bf16(v, h, l);
        ho[(size_t)(n0 + ty + 8 * i) * K + k0 + tx] = h;
        lo[(size_t)(n0 + ty + 8 * i) * K + k0 + tx] = l;
    }
}

// ---------------- LayerNorm ----------------------------------------------------
__global__ void ln_kernel(const float* __restrict__ x, const float* __restrict__ g,
                          const float* __restrict__ b, float* __restrict__ y,
                          __nv_bfloat16* __restrict__ yh, __nv_bfloat16* __restrict__ yl)
{
    int row = blockIdx.x;
    int tid = threadIdx.x;
    const float* xr = x + (size_t)row * DIM;

    float v0 = xr[tid];
    float v1 = xr[tid + 256];
    float s  = v0 + v1;
    float ss = v0 * v0 + v1 * v1;
    #pragma unroll
    for (int o = 16; o; o >>= 1) {
        s  += __shfl_xor_sync(0xffffffffu, s,  o);
        ss += __shfl_xor_sync(0xffffffffu, ss, o);
    }
    __shared__ float ws[8], wss[8];
    int w = tid >> 5, ln = tid & 31;
    if (ln == 0) { ws[w] = s; wss[w] = ss; }
    __syncthreads();
    __shared__ float s_mu, s_rstd;
    if (tid == 0) {
        float S = 0.f, SS = 0.f;
        #pragma unroll
        for (int i = 0; i < 8; i++) { S += ws[i]; SS += wss[i]; }
        float mu  = S * (1.0f / DIM);
        float var = SS * (1.0f / DIM) - mu * mu;
        s_mu = mu; s_rstd = rsqrtf(var + 1e-5f);
    }
    __syncthreads();
    float mu = s_mu, rstd = s_rstd;
    float o0 = (v0 - mu) * rstd * g[tid]       + b[tid];
    float o1 = (v1 - mu) * rstd * g[tid + 256] + b[tid + 256];
    size_t base = (size_t)row * DIM;
    if (y) {
        y[base + tid]       = o0;
        y[base + tid + 256] = o1;
    }
    if (yh) {
        __nv_bfloat16 h0, l0, h1, l1;
        split_bf16(o0, h0, l0);
        split_bf16(o1, h1, l1);
        yh[base + tid]       = h0;
        yh[base + tid + 256] = h1;
        yl[base + tid]       = l0;
        yl[base + tid + 256] = l1;
    }
}

// ---------------- RoPE ---------------------------------------------------------
__global__ void rope_kernel(float* __restrict__ q, float* __restrict__ k)
{
    int idx = blockIdx.x * blockDim.x + threadIdx.x;
    int d  = idx & 31;
    int h  = (idx >> 5) & (NH - 1);
    int bt = idx >> 8;
    int t  = bt & (SEQ - 1);

    float inv_freq = __powf(10000.0f, -(float)(2 * d) / (float)DH);
    float ang = (float)t * inv_freq;
    float c, s;
    sincosf(ang, &s, &c);

    size_t base = (size_t)bt * DIM + h * DH + d;

    float q1 = q[base], q2 = q[base + 32];
    q[base]      = q1 * c - q2 * s;
    q[base + 32] = q2 * c + q1 * s;

    float k1 = k[base], k2 = k[base + 32];
    k[base]      = k1 * c - k2 * s;
    k[base + 32] = k2 * c + k1 * s;
}

// ---------------- mma-based sliding-window attention ---------------------------
// Block = 64 queries of one (b,h). 5 K-tiles of 64. All math on tensor cores
// with bf16 hi/lo 3-term splits; softmax in fp32 smem.
#define QT    64
#define KSPAN 320
#define SPAD  324
#define TSTR  72           // bf16 tile row stride (elems) -> 144B, ldmatrix conflict-free

// byte offsets in dynamic smem
#define A2_QH   0
#define A2_QL   9216
#define A2_KH   18432      // reused as PH in phase 3
#define A2_KL   27648      // reused as PL
#define A2_VH   36864
#define A2_VL   46080
#define A2_S    55296      // fp32 [64][324]
#define A2_LINV 138240
#define A2_BYTES 138496

__global__ void __launch_bounds__(256)
attn_kernel(const float* __restrict__ q, const float* __restrict__ k,
            const float* __restrict__ v,
            __nv_bfloat16* __restrict__ oh, __nv_bfloat16* __restrict__ ol)
{
    extern __shared__ char sm[];
    __nv_bfloat16* QH = (__nv_bfloat16*)(sm + A2_QH);
    __nv_bfloat16* QL = (__nv_bfloat16*)(sm + A2_QL);
    __nv_bfloat16* KH = (__nv_bfloat16*)(sm + A2_KH);   // also PH
    __nv_bfloat16* KL = (__nv_bfloat16*)(sm + A2_KL);   // also PL
    __nv_bfloat16* VH = (__nv_bfloat16*)(sm + A2_VH);
    __nv_bfloat16* VL = (__nv_bfloat16*)(sm + A2_VL);
    float* S    = (float*)(sm + A2_S);
    float* linv = (float*)(sm + A2_LINV);

    uint32_t uQH = smem_u32(QH), uQL = smem_u32(QL);
    uint32_t uKH = smem_u32(KH), uKL = smem_u32(KL);
    uint32_t uVH = smem_u32(VH), uVL = smem_u32(VL);

    int tid  = threadIdx.x;
    int wid  = tid >> 5, lane = tid & 31;
    int mw   = (wid & 3) * 16;       // warp query offset
    int nw   = (wid >> 2) * 32;      // warp key/d offset

    int t0  = blockIdx.x * QT;
    int bh  = blockIdx.y;
    int b   = bh >> 3;
    int h   = bh & 7;
    int jbase = t0 - 256;

    // fragment addressing (same scheme as gemm_mm)
    int a_row  = mw + (lane & 15);
    int a_koff = (lane >> 4) * 8;
    int b_row  = nw + (lane & 7) + ((lane >> 4) & 1) * 8;
    int b_koff = ((lane >> 3) & 1) * 8;

    // ---- load Q tile (scaled 1/8), split hi/lo ----
    #pragma unroll
    for (int it = 0; it < 4; it++) {
        int vi  = tid + 256 * it;        // 0..1023 float4s
        int row = vi >> 4, c4 = (vi & 15) * 4;
        float4 f = *reinterpret_cast<const float4*>(
            q + (size_t)(b * SEQ + t0 + row) * DIM + h * DH + c4);
        f.x *= 0.125f; f.y *= 0.125f; f.z *= 0.125f; f.w *= 0.125f;
        __nv_bfloat16 h0,l0,h1,l1,h2,l2,h3,l3;
        split_bf16(f.x, h0, l0); split_bf16(f.y, h1, l1);
        split_bf16(f.z, h2, l2); split_bf16(f.w, h3, l3);
        __nv_bfloat162 hh0; hh0.x=h0; hh0.y=h1;
        __nv_bfloat162 hh1; hh1.x=h2; hh1.y=h3;
        __nv_bfloat162 ll0; ll0.x=l0; ll0.y=l1;
        __nv_bfloat162 ll1; ll1.x=l2; ll1.y=l3;
        int o = row * TSTR + c4;
        *reinterpret_cast<__nv_bfloat162*>(QH + o)     = hh0;
        *reinterpret_cast<__nv_bfloat162*>(QH + o + 2) = hh1;
        *reinterpret_cast<__nv_bfloat162*>(QL + o)     = ll0;
        *reinterpret_cast<__nv_bfloat162*>(QL + o + 2) = ll1;
    }

    // ---- phase 1: scores via mma ----
    for (int s = 0; s < 5; s++) {
        int kb = jbase + s * 64;
        __syncthreads();    // KH/KL reuse + (first iter) QH visibility
        #pragma unroll
        for (int it = 0; it < 4; it++) {
            int vi  = tid + 256 * it;
            int row = vi >> 4, c4 = (vi & 15) * 4;
            int j = kb + row;
            int jc = j < 0 ? 0 : j;
            float4 f = *reinterpret_cast<const float4*>(
                k + (size_t)(b * SEQ + jc) * DIM + h * DH + c4);
            __nv_bfloat16 h0,l0,h1,l1,h2,l2,h3,l3;
            split_bf16(f.x, h0, l0); split_bf16(f.y, h1, l1);
            split_bf16(f.z, h2, l2); split_bf16(f.w, h3, l3);
            __nv_bfloat162 hh0; hh0.x=h0; hh0.y=h1;
            __nv_bfloat162 hh1; hh1.x=h2; hh1.y=h3;
            __nv_bfloat162 ll0; ll0.x=l0; ll0.y=l1;
            __nv_bfloat162 ll1; ll1.x=l2; ll1.y=l3;
            int o = row * TSTR + c4;
            *reinterpret_cast<__nv_bfloat162*>(KH + o)     = hh0;
            *reinterpret_cast<__nv_bfloat162*>(KH + o + 2) = hh1;
            *reinterpret_cast<__nv_bfloat162*>(KL + o)     = ll0;
            *reinterpret_cast<__nv_bfloat162*>(KL + o + 2) = ll1;
        }
        __syncthreads();

        float acc[4][4];
        #pragma unroll
        for (int i = 0; i < 4; i++)
            #pragma unroll
            for (int j = 0; j < 4; j++) acc[i][j] = 0.f;

        #pragma unroll
        for (int k16 = 0; k16 < 4; k16++) {
            int kk0 = k16 * 16;
            uint32_t ah[4], al[4];
            uint32_t aoff = (a_row * TSTR + kk0 + a_koff) * 2;
            ldmx4(ah, uQH + aoff);
            ldmx4(al, uQL + aoff);
            #pragma unroll
            for (int ng = 0; ng < 2; ng++) {
                uint32_t bh2[4], bl2[4];
                uint32_t boff = ((b_row + ng * 16) * TSTR + kk0 + b_koff) * 2;
                ldmx4(bh2, uKH + boff);
                ldmx4(bl2, uKL + boff);
                mma_bf16(acc[2*ng],   ah, bh2);
                mma_bf16(acc[2*ng],   ah, bl2);
                mma_bf16(acc[2*ng],   al, bh2);
                mma_bf16(acc[2*ng+1], ah, bh2 + 2);
                mma_bf16(acc[2*ng+1], ah, bl2 + 2);
                mma_bf16(acc[2*ng+1], al, bh2 + 2);
            }
        }

        // masked store to S
        #pragma unroll
        for (int nt = 0; nt < 4; nt++) {
            #pragma unroll
            for (int half = 0; half < 2; half++) {
                int r = mw + (lane >> 2) + half * 8;
                int c = nw + nt * 8 + (lane & 3) * 2;
                int ig = t0 + r;
                #pragma unroll
                for (int e = 0; e < 2; e++) {
                    int jg = kb + c + e;
                    bool ok = (jg >= 0) && (jg <= ig) && (ig - jg < WIN);
                    S[r * SPAD + s * 64 + c + e] = ok ? acc[nt][half * 2 + e] : -INFINITY;
                }
            }
        }
    }
    __syncthreads();

    // ---- phase 2: softmax (exp stored back to S) ----
    {
        int r = tid >> 2, p = tid & 3;
        float m = -INFINITY;
        for (int cc = p; cc < KSPAN; cc += 4) m = fmaxf(m, S[r * SPAD + cc]);
        m = fmaxf(m, __shfl_xor_sync(0xffffffffu, m, 1));
        m = fmaxf(m, __shfl_xor_sync(0xffffffffu, m, 2));
        float sum = 0.f;
        for (int cc = p; cc < KSPAN; cc += 4) {
            float e = __expf(S[r * SPAD + cc] - m);
            S[r * SPAD + cc] = e;
            sum += e;
        }
        sum += __shfl_xor_sync(0xffffffffu, sum, 1);
        sum += __shfl_xor_sync(0xffffffffu, sum, 2);
        if (p == 0) linv[r] = 1.0f / sum;
    }

    // ---- phase 3: O = P @ V via mma ----
    float o[4][4];
    #pragma unroll
    for (int i = 0; i < 4; i++)
        #pragma unroll
        for (int j = 0; j < 4; j++) o[i][j] = 0.f;

    for (int s = 0; s < 5; s++) {
        int kb = jbase + s * 64;
        __syncthreads();    // protect PH/PL (=KH/KL) and VH/VL reuse; S stable after first sync
        // convert P tile: S[r][s*64+c] -> PH/PL [r][c]
        #pragma unroll
        for (int it = 0; it < 4; it++) {
            int vi  = tid + 256 * it;
            int row = vi >> 4, c4 = (vi & 15) * 4;
            float4 f = *reinterpret_cast<const float4*>(&S[row * SPAD + s * 64 + c4]);
            __nv_bfloat16 h0,l0,h1,l1,h2,l2,h3,l3;
            split_bf16(f.x, h0, l0); split_bf16(f.y, h1, l1);
            split_bf16(f.z, h2, l2); split_bf16(f.w, h3, l3);
            __nv_bfloat162 hh0; hh0.x=h0; hh0.y=h1;
            __nv_bfloat162 hh1; hh1.x=h2; hh1.y=h3;
            __nv_bfloat162 ll0; ll0.x=l0; ll0.y=l1;
            __nv_bfloat162 ll1; ll1.x=l2; ll1.y=l3;
            int oo = row * TSTR + c4;
            *reinterpret_cast<__nv_bfloat162*>(KH + oo)     = hh0;
            *reinterpret_cast<__nv_bfloat162*>(KH + oo + 2) = hh1;
            *reinterpret_cast<__nv_bfloat162*>(KL + oo)     = ll0;
            *reinterpret_cast<__nv_bfloat162*>(KL + oo + 2) = ll1;
        }
        // load V tile transposed: v[key][d] -> VH/VL [d][key]
        #pragma unroll
        for (int it = 0; it < 4; it++) {
            int vi  = tid + 256 * it;
            int kk = vi >> 4, c4 = (vi & 15) * 4;
            int j = kb + kk;
            int jc = j < 0 ? 0 : j;
            float4 f = *reinterpret_cast<const float4*>(
                v + (size_t)(b * SEQ + jc) * DIM + h * DH + c4);
            float fv[4] = {f.x, f.y, f.z, f.w};
            #pragma unroll
            for (int e = 0; e < 4; e++) {
                __nv_bfloat16 hh, ll;
                split_bf16(fv[e], hh, ll);
                VH[(c4 + e) * TSTR + kk] = hh;
                VL[(c4 + e) * TSTR + kk] = ll;
            }
        }
        __syncthreads();

        #pragma unroll
        for (int k16 = 0; k16 < 4; k16++) {
            int kk0 = k16 * 16;
            uint32_t ah[4], al[4];
            uint32_t aoff = (a_row * TSTR + kk0 + a_koff) * 2;
            ldmx4(ah, uKH + aoff);
            ldmx4(al, uKL + aoff);
            #pragma unroll
            for (int ng = 0; ng < 2; ng++) {
                uint32_t bh2[4], bl2[4];
                uint32_t boff = ((b_row + ng * 16) * TSTR + kk0 + b_koff) * 2;
                ldmx4(bh2, uVH + boff);
                ldmx4(bl2, uVL + boff);
                mma_bf16(o[2*ng],   ah, bh2);
                mma_bf16(o[2*ng],   ah, bl2);
                mma_bf16(o[2*ng],   al, bh2);
                mma_bf16(o[2*ng+1], ah, bh2 + 2);
                mma_bf16(o[2*ng+1], ah, bl2 + 2);
                mma_bf16(o[2*ng+1], al, bh2 + 2);
            }
        }
    }

    // ---- write out (bf16 hi/lo) ----
    #pragma unroll
    for (int nt = 0; nt < 4; nt++) {
        #pragma unroll
        for (int half = 0; half < 2; half++) {
            int r = mw + (lane >> 2) + half * 8;
            int d = nw + nt * 8 + (lane & 3) * 2;
            float li = linv[r];
            float v0 = o[nt][half * 2 + 0] * li;
            float v1 = o[nt][half * 2 + 1] * li;
            __nv_bfloat16 h0, l0, h1, l1;
            split_bf16(v0, h0, l0);
            split_bf16(v1, h1, l1);
            size_t base = (size_t)(b * SEQ + t0 + r) * DIM + h * DH + d;
            __nv_bfloat162 hh; hh.x = h0; hh.y = h1;
            __nv_bfloat162 ll; ll.x = l0; ll.y = l1;
            *reinterpret_cast<__nv_bfloat162*>(oh + base) = hh;
            *reinterpret_cast<__nv_bfloat162*>(ol + base) = ll;
        }
    }
}

// ---------------- host launcher ----------------------------------------------
extern "C" void kernel_launch(void* const* d_in, const int* in_sizes, int n_in,
                              void* d_out, int out_size)
{
    const float* tokens = (const float*)d_in[0];
    const float* Wq = (const float*)d_in[1];
    const float* Wk = (const float*)d_in[2];
    const float* Wv = (const float*)d_in[3];
    const float* Wo = (const float*)d_in[4];
    const float* bq = (const float*)d_in[5];
    const float* bk = (const float*)d_in[6];
    const float* bv = (const float*)d_in[7];
    const float* bo = (const float*)d_in[8];
    const float* W1 = (const float*)d_in[9];
    const float* b1 = (const float*)d_in[10];
    const float* W2 = (const float*)d_in[11];
    const float* b2 = (const float*)d_in[12];
    const float* g1 = (const float*)d_in[13];
    const float* be1= (const float*)d_in[14];
    const float* g2 = (const float*)d_in[15];
    const float* be2= (const float*)d_in[16];
    const float* gf = (const float*)d_in[17];
    const float* bf = (const float*)d_in[18];

    float *x, *q, *k, *v;
    cudaGetSymbolAddress((void**)&x, g_x);
    cudaGetSymbolAddress((void**)&q, g_q);
    cudaGetSymbolAddress((void**)&k, g_k);
    cudaGetSymbolAddress((void**)&v, g_v);

    __nv_bfloat16 *xnh, *xnl, *atth, *attl, *hbh, *hbl;
    cudaGetSymbolAddress((void**)&xnh,  g_xnh);
    cudaGetSymbolAddress((void**)&xnl,  g_xnl);
    cudaGetSymbolAddress((void**)&atth, g_atth);
    cudaGetSymbolAddress((void**)&attl, g_attl);
    cudaGetSymbolAddress((void**)&hbh,  g_hbh);
    cudaGetSymbolAddress((void**)&hbl,  g_hbl);

    __nv_bfloat16 *wqh,*wql,*wkh,*wkl,*wvh,*wvl,*woh,*wol,*w1h,*w1l,*w2h,*w2l;
    cudaGetSymbolAddress((void**)&wqh, g_wqt_h); cudaGetSymbolAddress((void**)&wql, g_wqt_l);
    cudaGetSymbolAddress((void**)&wkh, g_wkt_h); cudaGetSymbolAddress((void**)&wkl, g_wkt_l);
    cudaGetSymbolAddress((void**)&wvh, g_wvt_h); cudaGetSymbolAddress((void**)&wvl, g_wvt_l);
    cudaGetSymbolAddress((void**)&woh, g_wot_h); cudaGetSymbolAddress((void**)&wol, g_wot_l);
    cudaGetSymbolAddress((void**)&w1h, g_w1t_h); cudaGetSymbolAddress((void**)&w1l, g_w1t_l);
    cudaGetSymbolAddress((void**)&w2h, g_w2t_h); cudaGetSymbolAddress((void**)&w2l, g_w2t_l);

    cudaFuncSetAttribute(attn_kernel, cudaFuncAttributeMaxDynamicSharedMemorySize,
                         A2_BYTES);
    cudaFuncSetAttribute(qkv_mm, cudaFuncAttributeMaxDynamicSharedMemorySize, DSM_BYTES);
    cudaFuncSetAttribute(gemm_mm<0,1,1,0>, cudaFuncAttributeMaxDynamicSharedMemorySize, DSM_BYTES);
    cudaFuncSetAttribute(gemm_mm<1,0,0,1>, cudaFuncAttributeMaxDynamicSharedMemorySize, DSM_BYTES);

    cudaMemcpyAsync(x, tokens, sizeof(float) * (size_t)BT * DIM,
                    cudaMemcpyDeviceToDevice, 0);

    // weight conversion (all layers)
    {
        dim3 blk(32, 8);
        dim3 gdd(DIM / 32, DIM / 32, NL);
        wconv_kernel<<<gdd, blk>>>(Wq, wqh, wql, DIM, DIM);
        wconv_kernel<<<gdd, blk>>>(Wk, wkh, wkl, DIM, DIM);
        wconv_kernel<<<gdd, blk>>>(Wv, wvh, wvl, DIM, DIM);
        wconv_kernel<<<gdd, blk>>>(Wo, woh, wol, DIM, DIM);
        dim3 g1d(DFF / 32, DIM / 32, NL);
        wconv_kernel<<<g1d, blk>>>(W1, w1h, w1l, DIM, DFF);
        dim3 g2d(DIM / 32, DFF / 32, NL);
        wconv_kernel<<<g2d, blk>>>(W2, w2h, w2l, DFF, DIM);
    }

    dim3 gQKV(DIM / 128, BT / 128, 3);
    dim3 gD  (DIM / 128, BT / 128);
    dim3 gF  (DFF / 128, BT / 128);
    dim3 gAtt(SEQ / QT, BATCH * NH);

    for (int l = 0; l < NL; l++) {
        size_t wofs  = (size_t)l * DIM * DIM;
        size_t w1ofs = (size_t)l * DIM * DFF;

        ln_kernel<<<BT, 256>>>(x, g1 + l * DIM, be1 + l * DIM, nullptr, xnh, xnl);

        qkv_mm<<<gQKV, 256, DSM_BYTES>>>(xnh, xnl,
                                         wqh + wofs, wql + wofs,
                                         wkh + wofs, wkl + wofs,
                                         wvh + wofs, wvl + wofs,
                                         bq + l * DIM, bk + l * DIM, bv + l * DIM,
                                         q, k, v);

        rope_kernel<<<(BT * NH * 32) / 256, 256>>>(q, k);

        attn_kernel<<<gAtt, 256, A2_BYTES>>>(q, k, v, atth, attl);

        gemm_mm<0,1,1,0><<<gD, 256, DSM_BYTES>>>(atth, attl, woh + wofs, wol + wofs,
                                                 bo + l * DIM, x, x, nullptr, nullptr,
                                                 DIM, DIM);

        ln_kernel<<<BT, 256>>>(x, g2 + l * DIM, be2 + l * DIM, nullptr, xnh, xnl);

        gemm_mm<1,0,0,1><<<gF, 256, DSM_BYTES>>>(xnh, xnl, w1h + w1ofs, w1l + w1ofs,
                                                 b1 + l * DFF, nullptr, nullptr, hbh, hbl,
                                                 DFF, DIM);

        gemm_mm<0,1,1,0><<<gD, 256, DSM_BYTES>>>(hbh, hbl, w2h + w1ofs, w2l + w1ofs,
                                                 b2 + l * DIM, x, x, nullptr, nullptr,
                                                 DIM, DFF);
    }

    ln_kernel<<<BT, 256>>>(x, gf, bf, (float*)d_out, nullptr, nullptr);
}

// round 7
// speedup vs baseline: 3.6152x; 1.0232x over previous
#include <cuda_runtime.h>
#include <cuda_bf16.h>
#include <math.h>
#include <stdint.h>

#define BATCH 2
#define SEQ   2048
#define DIM   512
#define NH    8
#define DH    64
#define NL    4
#define DFF   2048
#define WIN   256
#define BT    (BATCH*SEQ)   // 4096

// ---------------- scratch (static device globals; no allocation) -------------
__device__ float g_x [BT*DIM];
__device__ float g_q [BT*DIM];
__device__ float g_k [BT*DIM];
__device__ float g_v [BT*DIM];

__device__ __nv_bfloat16 g_xnh [BT*DIM];
__device__ __nv_bfloat16 g_xnl [BT*DIM];
__device__ __nv_bfloat16 g_atth[BT*DIM];
__device__ __nv_bfloat16 g_attl[BT*DIM];
__device__ __nv_bfloat16 g_hbh [BT*DFF];
__device__ __nv_bfloat16 g_hbl [BT*DFF];

// attention operands (pre-split)
__device__ __nv_bfloat16 g_qh [BT*DIM], g_ql [BT*DIM];
__device__ __nv_bfloat16 g_kh [BT*DIM], g_kl [BT*DIM];
__device__ __nv_bfloat16 g_vth[BT*DIM], g_vtl[BT*DIM];   // [b*512+d][SEQ]

// transposed split weights: [L][N][K]
__device__ __nv_bfloat16 g_wqt_h[NL*DIM*DIM],  g_wqt_l[NL*DIM*DIM];
__device__ __nv_bfloat16 g_wkt_h[NL*DIM*DIM],  g_wkt_l[NL*DIM*DIM];
__device__ __nv_bfloat16 g_wvt_h[NL*DIM*DIM],  g_wvt_l[NL*DIM*DIM];
__device__ __nv_bfloat16 g_wot_h[NL*DIM*DIM],  g_wot_l[NL*DIM*DIM];
__device__ __nv_bfloat16 g_w1t_h[NL*DIM*DFF],  g_w1t_l[NL*DIM*DFF];
__device__ __nv_bfloat16 g_w2t_h[NL*DFF*DIM],  g_w2t_l[NL*DFF*DIM];

// ---------------- PTX helpers --------------------------------------------------
__device__ __forceinline__ uint32_t smem_u32(const void* p) {
    uint32_t a;
    asm("{ .reg .u64 t; cvta.to.shared.u64 t, %1; cvt.u32.u64 %0, t; }"
        : "=r"(a) : "l"(p));
    return a;
}

__device__ __forceinline__ void cpa16(uint32_t dst, const void* src)
{
    asm volatile("cp.async.cg.shared.global [%0], [%1], 16;" :: "r"(dst), "l"(src));
}

__device__ __forceinline__ void ldmx4(uint32_t* r, uint32_t addr)
{
    asm volatile("ldmatrix.sync.aligned.m8n8.x4.shared.b16 {%0,%1,%2,%3}, [%4];"
        : "=r"(r[0]), "=r"(r[1]), "=r"(r[2]), "=r"(r[3]) : "r"(addr));
}

__device__ __forceinline__ void mma_bf16(float* c, const uint32_t* a, const uint32_t* b)
{
    asm volatile(
        "mma.sync.aligned.m16n8k16.row.col.f32.bf16.bf16.f32 "
        "{%0,%1,%2,%3}, {%4,%5,%6,%7}, {%8,%9}, {%0,%1,%2,%3};"
        : "+f"(c[0]), "+f"(c[1]), "+f"(c[2]), "+f"(c[3])
        : "r"(a[0]), "r"(a[1]), "r"(a[2]), "r"(a[3]), "r"(b[0]), "r"(b[1]));
}

__device__ __forceinline__ void split_bf16(float v, __nv_bfloat16& h, __nv_bfloat16& l)
{
    h = __float2bfloat16(v);
    l = __float2bfloat16(v - __bfloat162float(h));
}

// ---------------- mma.sync bf16-split GEMM (3-stage cp.async) ------------------
#define TKC       32
#define RSTR      40
#define ARR_BYTES (128*RSTR*2)
#define STG_BYTES (4*ARR_BYTES)       // 40960
#define DSM_BYTES (3*STG_BYTES)       // 122880

template <int GELU, int RES, int OUTF32, int OUTBF>
__device__ __forceinline__ void gemm_mm_core(
    const __nv_bfloat16* __restrict__ Ah, const __nv_bfloat16* __restrict__ Al,
    const __nv_bfloat16* __restrict__ Bh, const __nv_bfloat16* __restrict__ Bl,
    const float* __restrict__ bias, const float* __restrict__ res,
    float* __restrict__ C, __nv_bfloat16* __restrict__ Oh, __nv_bfloat16* __restrict__ Ol,
    int N, int K, int m0, int n0)
{
    extern __shared__ char dsm[];
    uint32_t sm0 = smem_u32(dsm);

    int tid  = threadIdx.x;
    int wid  = tid >> 5, lane = tid & 31;
    int mw   = (wid & 3) * 32;
    int nw   = (wid >> 2) * 64;

    float acc[2][8][4];
    #pragma unroll
    for (int i = 0; i < 2; i++)
        #pragma unroll
        for (int j = 0; j < 8; j++)
            #pragma unroll
            for (int t = 0; t < 4; t++) acc[i][j][t] = 0.f;

    int nk = K / TKC;

    auto load_stage = [&](int c) {
        int st = c % 3;
        uint32_t sb = sm0 + st * STG_BYTES;
        int k0 = c * TKC;
        #pragma unroll
        for (int it = 0; it < 8; it++) {
            int idx  = it * 256 + tid;
            int arr  = idx >> 9;
            int rem  = idx & 511;
            int row  = rem >> 2;
            int part = rem & 3;
            uint32_t dst = sb + arr * ARR_BYTES + row * (RSTR * 2) + part * 16;
            const __nv_bfloat16* src;
            if      (arr == 0) src = Ah + (size_t)(m0 + row) * K + k0 + part * 8;
            else if (arr == 1) src = Al + (size_t)(m0 + row) * K + k0 + part * 8;
            else if (arr == 2) src = Bh + (size_t)(n0 + row) * K + k0 + part * 8;
            else               src = Bl + (size_t)(n0 + row) * K + k0 + part * 8;
            cpa16(dst, src);
        }
        asm volatile("cp.async.commit_group;" ::: "memory");
    };

    load_stage(0);
    load_stage(1);

    int a_row = mw + (lane & 15);
    int a_koff = (lane >> 4) * 8;
    int b_row = nw + (lane & 7) + ((lane >> 4) & 1) * 8;
    int b_koff = ((lane >> 3) & 1) * 8;

    for (int c = 0; c < nk; c++) {
        if (c + 2 < nk) load_stage(c + 2);

        if (c + 2 < nk)      asm volatile("cp.async.wait_group 2;" ::: "memory");
        else if (c + 1 < nk) asm volatile("cp.async.wait_group 1;" ::: "memory");
        else                 asm volatile("cp.async.wait_group 0;" ::: "memory");
        __syncthreads();

        uint32_t sb  = sm0 + (c % 3) * STG_BYTES;
        uint32_t sah = sb;
        uint32_t sal = sb + ARR_BYTES;
        uint32_t sbh = sb + 2 * ARR_BYTES;
        uint32_t sbl = sb + 3 * ARR_BYTES;

        #pragma unroll
        for (int h = 0; h < 2; h++) {
            int k0 = h * 16;
            uint32_t ah[2][4], al[2][4];
            #pragma unroll
            for (int mt = 0; mt < 2; mt++) {
                uint32_t off = ((a_row + mt * 16) * RSTR + k0 + a_koff) * 2;
                ldmx4(ah[mt], sah + off);
                ldmx4(al[mt], sal + off);
            }
            #pragma unroll
            for (int ng = 0; ng < 4; ng++) {
                uint32_t bh[4], bl[4];
                uint32_t off = ((b_row + ng * 16) * RSTR + k0 + b_koff) * 2;
                ldmx4(bh, sbh + off);
                ldmx4(bl, sbl + off);
                #pragma unroll
                for (int mt = 0; mt < 2; mt++) {
                    mma_bf16(acc[mt][2*ng],   ah[mt], bh);
                    mma_bf16(acc[mt][2*ng],   ah[mt], bl);
                    mma_bf16(acc[mt][2*ng],   al[mt], bh);
                    mma_bf16(acc[mt][2*ng+1], ah[mt], bh + 2);
                    mma_bf16(acc[mt][2*ng+1], ah[mt], bl + 2);
                    mma_bf16(acc[mt][2*ng+1], al[mt], bh + 2);
                }
            }
        }
        __syncthreads();
    }

    int cbase_n = n0 + nw + (lane & 3) * 2;
    #pragma unroll
    for (int mt = 0; mt < 2; mt++) {
        #pragma unroll
        for (int half = 0; half < 2; half++) {
            int row = m0 + mw + mt * 16 + (lane >> 2) + half * 8;
            size_t rbase = (size_t)row * N;
            #pragma unroll
            for (int nt = 0; nt < 8; nt++) {
                int col = cbase_n + nt * 8;
                float v0 = acc[mt][nt][half * 2 + 0];
                float v1 = acc[mt][nt][half * 2 + 1];
                float2 b2 = *reinterpret_cast<const float2*>(bias + col);
                v0 += b2.x; v1 += b2.y;
                if (GELU) {
                    v0 = 0.5f * v0 * (1.0f + erff(v0 * 0.70710678118654752f));
                    v1 = 0.5f * v1 * (1.0f + erff(v1 * 0.70710678118654752f));
                }
                if (RES) {
                    float2 r2 = *reinterpret_cast<const float2*>(res + rbase + col);
                    v0 += r2.x; v1 += r2.y;
                }
                if (OUTF32) {
                    *reinterpret_cast<float2*>(C + rbase + col) = make_float2(v0, v1);
                }
                if (OUTBF) {
                    __nv_bfloat16 h0, l0, h1, l1;
                    split_bf16(v0, h0, l0);
                    split_bf16(v1, h1, l1);
                    __nv_bfloat162 hh; hh.x = h0; hh.y = h1;
                    __nv_bfloat162 ll; ll.x = l0; ll.y = l1;
                    *reinterpret_cast<__nv_bfloat162*>(Oh + rbase + col) = hh;
                    *reinterpret_cast<__nv_bfloat162*>(Ol + rbase + col) = ll;
                }
            }
        }
    }
}

template <int GELU, int RES, int OUTF32, int OUTBF>
__global__ void __launch_bounds__(256, 1)
gemm_mm(const __nv_bfloat16* __restrict__ Ah, const __nv_bfloat16* __restrict__ Al,
        const __nv_bfloat16* __restrict__ Bh, const __nv_bfloat16* __restrict__ Bl,
        const float* __restrict__ bias, const float* __restrict__ res,
        float* __restrict__ C, __nv_bfloat16* __restrict__ Oh,
        __nv_bfloat16* __restrict__ Ol, int N, int K)
{
    gemm_mm_core<GELU, RES, OUTF32, OUTBF>(Ah, Al, Bh, Bl, bias, res, C, Oh, Ol,
                                           N, K, blockIdx.y * 128, blockIdx.x * 128);
}

__global__ void __launch_bounds__(256, 1)
qkv_mm(const __nv_bfloat16* __restrict__ Ah, const __nv_bfloat16* __restrict__ Al,
       const __nv_bfloat16* __restrict__ Bqh, const __nv_bfloat16* __restrict__ Bql,
       const __nv_bfloat16* __restrict__ Bkh, const __nv_bfloat16* __restrict__ Bkl,
       const __nv_bfloat16* __restrict__ Bvh, const __nv_bfloat16* __restrict__ Bvl,
       const float* __restrict__ bq, const float* __restrict__ bk,
       const float* __restrict__ bv,
       float* __restrict__ q, float* __restrict__ k, float* __restrict__ v)
{
    int z = blockIdx.z;
    const __nv_bfloat16* Bh = (z == 0) ? Bqh : (z == 1) ? Bkh : Bvh;
    const __nv_bfloat16* Bl = (z == 0) ? Bql : (z == 1) ? Bkl : Bvl;
    const float* bi = (z == 0) ? bq : (z == 1) ? bk : bv;
    float* C        = (z == 0) ? q  : (z == 1) ? k  : v;
    gemm_mm_core<0, 0, 1, 0>(Ah, Al, Bh, Bl, bi, nullptr, C, nullptr, nullptr,
                             DIM, DIM, blockIdx.y * 128, blockIdx.x * 128);
}

// ---------------- weight transpose + bf16 split -------------------------------
__global__ void wconv_kernel(const float* __restrict__ W,
                             __nv_bfloat16* __restrict__ hiT,
                             __nv_bfloat16* __restrict__ loT, int K, int N)
{
    __shared__ float t[32][33];
    int n0 = blockIdx.x * 32, k0 = blockIdx.y * 32;
    size_t lofs = (size_t)blockIdx.z * K * N;
    const float* Wl = W + lofs;
    int tx = threadIdx.x, ty = threadIdx.y;
    #pragma unroll
    for (int i = 0; i < 4; i++)
        t[ty + 8 * i][tx] = Wl[(size_t)(k0 + ty + 8 * i) * N + n0 + tx];
    __syncthreads();
    __nv_bfloat16* ho = hiT + lofs;
    __nv_bfloat16* lo = loT + lofs;
    #pragma unroll
    for (int i = 0; i < 4; i++) {
        float v = t[tx][ty + 8 * i];
        __nv_bfloat16 h, l;
        split_bf16(v, h, l);
        ho[(size_t)(n0 + ty + 8 * i) * K + k0 + tx] = h;
        lo[(size_t)(n0 + ty + 8 * i) * K + k0 + tx] = l;
    }
}

// ---------------- V transpose + split: v[b,t,d] -> vt[(b*512+d)][t] -----------
__global__ void vconv_kernel(const float* __restrict__ v,
                             __nv_bfloat16* __restrict__ vth,
                             __nv_bfloat16* __restrict__ vtl)
{
    __shared__ float t[32][33];
    int t0 = blockIdx.x * 32, d0 = blockIdx.y * 32, b = blockIdx.z;
    int tx = threadIdx.x, ty = threadIdx.y;
    #pragma unroll
    for (int i = 0; i < 4; i++)
        t[ty + 8 * i][tx] = v[(size_t)(b * SEQ + t0 + ty + 8 * i) * DIM + d0 + tx];
    __syncthreads();
    #pragma unroll
    for (int i = 0; i < 4; i++) {
        float val = t[tx][ty + 8 * i];
        __nv_bfloat16 h, l;
        split_bf16(val, h, l);
        size_t o = (size_t)(b * DIM + d0 + ty + 8 * i) * SEQ + t0 + tx;
        vth[o] = h;
        vtl[o] = l;
    }
}

// ---------------- RoPE + scale + split for q,k --------------------------------
__global__ void ropesplit_kernel(const float* __restrict__ q, const float* __restrict__ k,
                                 __nv_bfloat16* __restrict__ qh, __nv_bfloat16* __restrict__ ql,
                                 __nv_bfloat16* __restrict__ kh, __nv_bfloat16* __restrict__ kl)
{
    int idx = blockIdx.x * blockDim.x + threadIdx.x;   // over BT*NH*32
    int d  = idx & 31;
    int h  = (idx >> 5) & (NH - 1);
    int bt = idx >> 8;
    int t  = bt & (SEQ - 1);

    float inv_freq = __powf(10000.0f, -(float)(2 * d) / (float)DH);
    float ang = (float)t * inv_freq;
    float c, s;
    sincosf(ang, &s, &c);

    size_t base = (size_t)bt * DIM + h * DH + d;

    float q1 = q[base], q2 = q[base + 32];
    float qo1 = (q1 * c - q2 * s) * 0.125f;
    float qo2 = (q2 * c + q1 * s) * 0.125f;
    __nv_bfloat16 hh, ll;
    split_bf16(qo1, hh, ll); qh[base] = hh;      ql[base] = ll;
    split_bf16(qo2, hh, ll); qh[base + 32] = hh; ql[base + 32] = ll;

    float k1 = k[base], k2 = k[base + 32];
    float ko1 = k1 * c - k2 * s;
    float ko2 = k2 * c + k1 * s;
    split_bf16(ko1, hh, ll); kh[base] = hh;      kl[base] = ll;
    split_bf16(ko2, hh, ll); kh[base + 32] = hh; kl[base + 32] = ll;
}

// ---------------- LayerNorm ----------------------------------------------------
__global__ void ln_kernel(const float* __restrict__ x, const float* __restrict__ g,
                          const float* __restrict__ b, float* __restrict__ y,
                          __nv_bfloat16* __restrict__ yh, __nv_bfloat16* __restrict__ yl)
{
    int row = blockIdx.x;
    int tid = threadIdx.x;
    const float* xr = x + (size_t)row * DIM;

    float v0 = xr[tid];
    float v1 = xr[tid + 256];
    float s  = v0 + v1;
    float ss = v0 * v0 + v1 * v1;
    #pragma unroll
    for (int o = 16; o; o >>= 1) {
        s  += __shfl_xor_sync(0xffffffffu, s,  o);
        ss += __shfl_xor_sync(0xffffffffu, ss, o);
    }
    __shared__ float ws[8], wss[8];
    int w = tid >> 5, ln = tid & 31;
    if (ln == 0) { ws[w] = s; wss[w] = ss; }
    __syncthreads();
    __shared__ float s_mu, s_rstd;
    if (tid == 0) {
        float S = 0.f, SS = 0.f;
        #pragma unroll
        for (int i = 0; i < 8; i++) { S += ws[i]; SS += wss[i]; }
        float mu  = S * (1.0f / DIM);
        float var = SS * (1.0f / DIM) - mu * mu;
        s_mu = mu; s_rstd = rsqrtf(var + 1e-5f);
    }
    __syncthreads();
    float mu = s_mu, rstd = s_rstd;
    float o0 = (v0 - mu) * rstd * g[tid]       + b[tid];
    float o1 = (v1 - mu) * rstd * g[tid + 256] + b[tid + 256];
    size_t base = (size_t)row * DIM;
    if (y) {
        y[base + tid]       = o0;
        y[base + tid + 256] = o1;
    }
    if (yh) {
        __nv_bfloat16 h0, l0, h1, l1;
        split_bf16(o0, h0, l0);
        split_bf16(o1, h1, l1);
        yh[base + tid]       = h0;
        yh[base + tid + 256] = h1;
        yl[base + tid]       = l0;
        yl[base + tid + 256] = l1;
    }
}

// ---------------- mma attention, pre-split operands, cp.async pipelined -------
#define QT    64
#define KSPAN 320
#define SPAD  324
#define TSTR  72
#define TILE_B (64*TSTR*2)     // 9216 bytes per bf16 array

// dynamic smem byte offsets
#define A3_QH   0
#define A3_QL   9216
#define A3_K    18432          // K[2 bufs][hi,lo] = 4*9216 ; PH/PL reuse buf0
#define A3_V    55296          // V[2 bufs][hi,lo] = 4*9216
#define A3_S    92160          // fp32 [64][324] = 82944
#define A3_LINV 175104
#define A3_BYTES 175360

__global__ void __launch_bounds__(256)
attn_kernel(const __nv_bfloat16* __restrict__ qh, const __nv_bfloat16* __restrict__ ql,
            const __nv_bfloat16* __restrict__ kh, const __nv_bfloat16* __restrict__ kl,
            const __nv_bfloat16* __restrict__ vth, const __nv_bfloat16* __restrict__ vtl,
            __nv_bfloat16* __restrict__ oh, __nv_bfloat16* __restrict__ ol)
{
    extern __shared__ char sm[];
    float* S    = (float*)(sm + A3_S);
    float* linv = (float*)(sm + A3_LINV);
    __nv_bfloat16* PH = (__nv_bfloat16*)(sm + A3_K);
    __nv_bfloat16* PL = (__nv_bfloat16*)(sm + A3_K + TILE_B);

    uint32_t uQH = smem_u32(sm) + A3_QH;
    uint32_t uQL = smem_u32(sm) + A3_QL;
    uint32_t uK  = smem_u32(sm) + A3_K;
    uint32_t uV  = smem_u32(sm) + A3_V;

    int tid  = threadIdx.x;
    int wid  = tid >> 5, lane = tid & 31;
    int mw   = (wid & 3) * 16;
    int nw   = (wid >> 2) * 32;

    int t0  = blockIdx.x * QT;
    int bh  = blockIdx.y;
    int b   = bh >> 3;
    int h   = bh & 7;
    int jbase = t0 - 256;

    int a_row  = mw + (lane & 15);
    int a_koff = (lane >> 4) * 8;
    int b_row  = nw + (lane & 7) + ((lane >> 4) & 1) * 8;
    int b_koff = ((lane >> 3) & 1) * 8;

    // ---- Q load (group 0, with K(0)) ----
    {
        #pragma unroll
        for (int it = 0; it < 4; it++) {
            int vi  = tid + 256 * it;        // 0..1023
            int row = vi >> 4, c = vi & 15;
            const __nv_bfloat16* src = (c < 8 ? qh : ql)
                + (size_t)(b * SEQ + t0 + row) * DIM + h * DH + (c & 7) * 8;
            uint32_t dst = (c < 8 ? uQH : uQL) + row * (TSTR * 2) + (c & 7) * 16;
            cpa16(dst, src);
        }
    }

    auto load_k = [&](int s) {
        int kb = jbase + s * 64;
        uint32_t sb = uK + (s & 1) * (2 * TILE_B);
        #pragma unroll
        for (int it = 0; it < 4; it++) {
            int vi  = tid + 256 * it;
            int row = vi >> 4, c = vi & 15;
            int j = kb + row;
            int jc = j < 0 ? 0 : j;
            const __nv_bfloat16* src = (c < 8 ? kh : kl)
                + (size_t)(b * SEQ + jc) * DIM + h * DH + (c & 7) * 8;
            uint32_t dst = sb + (c < 8 ? 0 : TILE_B) + row * (TSTR * 2) + (c & 7) * 16;
            cpa16(dst, src);
        }
        asm volatile("cp.async.commit_group;" ::: "memory");
    };

    auto load_v = [&](int s) {
        int kb = jbase + s * 64;
        uint32_t sb = uV + (s & 1) * (2 * TILE_B);
        #pragma unroll
        for (int it = 0; it < 4; it++) {
            int vi  = tid + 256 * it;
            int row = vi >> 4, c = vi & 15;       // row = d (0..63)
            int j0 = kb + (c & 7) * 8;
            int jc = j0 < 0 ? 0 : j0;
            const __nv_bfloat16* src = (c < 8 ? vth : vtl)
                + (size_t)(b * DIM + h * DH + row) * SEQ + jc;
            uint32_t dst = sb + (c < 8 ? 0 : TILE_B) + row * (TSTR * 2) + (c & 7) * 16;
            cpa16(dst, src);
        }
        asm volatile("cp.async.commit_group;" ::: "memory");
    };

    // ---- phase 1: scores ----
    load_k(0);   // includes Q copies issued above (same group)
    load_k(1);

    for (int s = 0; s < 5; s++) {
        if (s < 4) asm volatile("cp.async.wait_group 1;" ::: "memory");
        else       asm volatile("cp.async.wait_group 0;" ::: "memory");
        __syncthreads();

        uint32_t sKH = uK + (s & 1) * (2 * TILE_B);
        uint32_t sKL = sKH + TILE_B;
        int kb = jbase + s * 64;

        float acc[4][4];
        #pragma unroll
        for (int i = 0; i < 4; i++)
            #pragma unroll
            for (int j = 0; j < 4; j++) acc[i][j] = 0.f;

        #pragma unroll
        for (int k16 = 0; k16 < 4; k16++) {
            int kk0 = k16 * 16;
            uint32_t ah[4], al[4];
            uint32_t aoff = (a_row * TSTR + kk0 + a_koff) * 2;
            ldmx4(ah, uQH + aoff);
            ldmx4(al, uQL + aoff);
            #pragma unroll
            for (int ng = 0; ng < 2; ng++) {
                uint32_t bh2[4], bl2[4];
                uint32_t boff = ((b_row + ng * 16) * TSTR + kk0 + b_koff) * 2;
                ldmx4(bh2, sKH + boff);
                ldmx4(bl2, sKL + boff);
                mma_bf16(acc[2*ng],   ah, bh2);
                mma_bf16(acc[2*ng],   ah, bl2);
                mma_bf16(acc[2*ng],   al, bh2);
                mma_bf16(acc[2*ng+1], ah, bh2 + 2);
                mma_bf16(acc[2*ng+1], ah, bl2 + 2);
                mma_bf16(acc[2*ng+1], al, bh2 + 2);
            }
        }

        #pragma unroll
        for (int nt = 0; nt < 4; nt++) {
            #pragma unroll
            for (int half = 0; half < 2; half++) {
                int r = mw + (lane >> 2) + half * 8;
                int c = nw + nt * 8 + (lane & 3) * 2;
                int ig = t0 + r;
                #pragma unroll
                for (int e = 0; e < 2; e++) {
                    int jg = kb + c + e;
                    bool ok = (jg >= 0) && (jg <= ig) && (ig - jg < WIN);
                    S[r * SPAD + s * 64 + c + e] = ok ? acc[nt][half * 2 + e] : -INFINITY;
                }
            }
        }
        __syncthreads();
        if (s + 2 < 5) load_k(s + 2);
    }
    __syncthreads();

    // ---- phase 2: softmax ----
    {
        int r = tid >> 2, p = tid & 3;
        float m = -INFINITY;
        for (int cc = p; cc < KSPAN; cc += 4) m = fmaxf(m, S[r * SPAD + cc]);
        m = fmaxf(m, __shfl_xor_sync(0xffffffffu, m, 1));
        m = fmaxf(m, __shfl_xor_sync(0xffffffffu, m, 2));
        float sum = 0.f;
        for (int cc = p; cc < KSPAN; cc += 4) {
            float e = __expf(S[r * SPAD + cc] - m);
            S[r * SPAD + cc] = e;
            sum += e;
        }
        sum += __shfl_xor_sync(0xffffffffu, sum, 1);
        sum += __shfl_xor_sync(0xffffffffu, sum, 2);
        if (p == 0) linv[r] = 1.0f / sum;
    }
    __syncthreads();

    // ---- phase 3: O = P @ V ----
    load_v(0);
    load_v(1);

    float o[4][4];
    #pragma unroll
    for (int i = 0; i < 4; i++)
        #pragma unroll
        for (int j = 0; j < 4; j++) o[i][j] = 0.f;

    // PH/PL occupy K buf0 region (uK .. uK+2*TILE_B); K no longer used.
    uint32_t uPH = uK, uPL = uK + TILE_B;

    for (int s = 0; s < 5; s++) {
        if (s < 4) asm volatile("cp.async.wait_group 1;" ::: "memory");
        else       asm volatile("cp.async.wait_group 0;" ::: "memory");
        __syncthreads();   // V(s) visible; previous iteration's P readers done

        // convert P tile s -> PH/PL
        #pragma unroll
        for (int it = 0; it < 4; it++) {
            int vi  = tid + 256 * it;
            int row = vi >> 4, c4 = (vi & 15) * 4;
            float4 f = *reinterpret_cast<const float4*>(&S[row * SPAD + s * 64 + c4]);
            __nv_bfloat16 h0,l0,h1,l1,h2,l2,h3,l3;
            split_bf16(f.x, h0, l0); split_bf16(f.y, h1, l1);
            split_bf16(f.z, h2, l2); split_bf16(f.w, h3, l3);
            __nv_bfloat162 hh0; hh0.x=h0; hh0.y=h1;
            __nv_bfloat162 hh1; hh1.x=h2; hh1.y=h3;
            __nv_bfloat162 ll0; ll0.x=l0; ll0.y=l1;
            __nv_bfloat162 ll1; ll1.x=l2; ll1.y=l3;
            int oo = row * TSTR + c4;
            *reinterpret_cast<__nv_bfloat162*>(PH + oo)     = hh0;
            *reinterpret_cast<__nv_bfloat162*>(PH + oo + 2) = hh1;
            *reinterpret_cast<__nv_bfloat162*>(PL + oo)     = ll0;
            *reinterpret_cast<__nv_bfloat162*>(PL + oo + 2) = ll1;
        }
        __syncthreads();

        uint32_t sVH = uV + (s & 1) * (2 * TILE_B);
        uint32_t sVL = sVH + TILE_B;

        #pragma unroll
        for (int k16 = 0; k16 < 4; k16++) {
            int kk0 = k16 * 16;
            uint32_t ah[4], al[4];
            uint32_t aoff = (a_row * TSTR + kk0 + a_koff) * 2;
            ldmx4(ah, uPH + aoff);
            ldmx4(al, uPL + aoff);
            #pragma unroll
            for (int ng = 0; ng < 2; ng++) {
                uint32_t bh2[4], bl2[4];
                uint32_t boff = ((b_row + ng * 16) * TSTR + kk0 + b_koff) * 2;
                ldmx4(bh2, sVH + boff);
                ldmx4(bl2, sVL + boff);
                mma_bf16(o[2*ng],   ah, bh2);
                mma_bf16(o[2*ng],   ah, bl2);
                mma_bf16(o[2*ng],   al, bh2);
                mma_bf16(o[2*ng+1], ah, bh2 + 2);
                mma_bf16(o[2*ng+1], ah, bl2 + 2);
                mma_bf16(o[2*ng+1], al, bh2 + 2);
            }
        }
        __syncthreads();   // all reads of V buf (s&1) and PH/PL done
        if (s + 2 < 5) load_v(s + 2);
    }

    // ---- write out ----
    #pragma unroll
    for (int nt = 0; nt < 4; nt++) {
        #pragma unroll
        for (int half = 0; half < 2; half++) {
            int r = mw + (lane >> 2) + half * 8;
            int d = nw + nt * 8 + (lane & 3) * 2;
            float li = linv[r];
            float v0 = o[nt][half * 2 + 0] * li;
            float v1 = o[nt][half * 2 + 1] * li;
            __nv_bfloat16 h0, l0, h1, l1;
            split_bf16(v0, h0, l0);
            split_bf16(v1, h1, l1);
            size_t base = (size_t)(b * SEQ + t0 + r) * DIM + h * DH + d;
            __nv_bfloat162 hh; hh.x = h0; hh.y = h1;
            __nv_bfloat162 ll; ll.x = l0; ll.y = l1;
            *reinterpret_cast<__nv_bfloat162*>(oh + base) = hh;
            *reinterpret_cast<__nv_bfloat162*>(ol + base) = ll;
        }
    }
}

// ---------------- host launcher ----------------------------------------------
extern "C" void kernel_launch(void* const* d_in, const int* in_sizes, int n_in,
                              void* d_out, int out_size)
{
    const float* tokens = (const float*)d_in[0];
    const float* Wq = (const float*)d_in[1];
    const float* Wk = (const float*)d_in[2];
    const float* Wv = (const float*)d_in[3];
    const float* Wo = (const float*)d_in[4];
    const float* bq = (const float*)d_in[5];
    const float* bk = (const float*)d_in[6];
    const float* bv = (const float*)d_in[7];
    const float* bo = (const float*)d_in[8];
    const float* W1 = (const float*)d_in[9];
    const float* b1 = (const float*)d_in[10];
    const float* W2 = (const float*)d_in[11];
    const float* b2 = (const float*)d_in[12];
    const float* g1 = (const float*)d_in[13];
    const float* be1= (const float*)d_in[14];
    const float* g2 = (const float*)d_in[15];
    const float* be2= (const float*)d_in[16];
    const float* gf = (const float*)d_in[17];
    const float* bf = (const float*)d_in[18];

    float *x, *q, *k, *v;
    cudaGetSymbolAddress((void**)&x, g_x);
    cudaGetSymbolAddress((void**)&q, g_q);
    cudaGetSymbolAddress((void**)&k, g_k);
    cudaGetSymbolAddress((void**)&v, g_v);

    __nv_bfloat16 *xnh, *xnl, *atth, *attl, *hbh, *hbl;
    cudaGetSymbolAddress((void**)&xnh,  g_xnh);
    cudaGetSymbolAddress((void**)&xnl,  g_xnl);
    cudaGetSymbolAddress((void**)&atth, g_atth);
    cudaGetSymbolAddress((void**)&attl, g_attl);
    cudaGetSymbolAddress((void**)&hbh,  g_hbh);
    cudaGetSymbolAddress((void**)&hbl,  g_hbl);

    __nv_bfloat16 *qh, *ql, *kh, *kl, *vth, *vtl;
    cudaGetSymbolAddress((void**)&qh,  g_qh);
    cudaGetSymbolAddress((void**)&ql,  g_ql);
    cudaGetSymbolAddress((void**)&kh,  g_kh);
    cudaGetSymbolAddress((void**)&kl,  g_kl);
    cudaGetSymbolAddress((void**)&vth, g_vth);
    cudaGetSymbolAddress((void**)&vtl, g_vtl);

    __nv_bfloat16 *wqh,*wql,*wkh,*wkl,*wvh,*wvl,*woh,*wol,*w1h,*w1l,*w2h,*w2l;
    cudaGetSymbolAddress((void**)&wqh, g_wqt_h); cudaGetSymbolAddress((void**)&wql, g_wqt_l);
    cudaGetSymbolAddress((void**)&wkh, g_wkt_h); cudaGetSymbolAddress((void**)&wkl, g_wkt_l);
    cudaGetSymbolAddress((void**)&wvh, g_wvt_h); cudaGetSymbolAddress((void**)&wvl, g_wvt_l);
    cudaGetSymbolAddress((void**)&woh, g_wot_h); cudaGetSymbolAddress((void**)&wol, g_wot_l);
    cudaGetSymbolAddress((void**)&w1h, g_w1t_h); cudaGetSymbolAddress((void**)&w1l, g_w1t_l);
    cudaGetSymbolAddress((void**)&w2h, g_w2t_h); cudaGetSymbolAddress((void**)&w2l, g_w2t_l);

    cudaFuncSetAttribute(attn_kernel, cudaFuncAttributeMaxDynamicSharedMemorySize,
                         A3_BYTES);
    cudaFuncSetAttribute(qkv_mm, cudaFuncAttributeMaxDynamicSharedMemorySize, DSM_BYTES);
    cudaFuncSetAttribute(gemm_mm<0,1,1,0>, cudaFuncAttributeMaxDynamicSharedMemorySize, DSM_BYTES);
    cudaFuncSetAttribute(gemm_mm<1,0,0,1>, cudaFuncAttributeMaxDynamicSharedMemorySize, DSM_BYTES);

    cudaMemcpyAsync(x, tokens, sizeof(float) * (size_t)BT * DIM,
                    cudaMemcpyDeviceToDevice, 0);

    // weight conversion
    {
        dim3 blk(32, 8);
        dim3 gdd(DIM / 32, DIM / 32, NL);
        wconv_kernel<<<gdd, blk>>>(Wq, wqh, wql, DIM, DIM);
        wconv_kernel<<<gdd, blk>>>(Wk, wkh, wkl, DIM, DIM);
        wconv_kernel<<<gdd, blk>>>(Wv, wvh, wvl, DIM, DIM);
        wconv_kernel<<<gdd, blk>>>(Wo, woh, wol, DIM, DIM);
        dim3 g1d(DFF / 32, DIM / 32, NL);
        wconv_kernel<<<g1d, blk>>>(W1, w1h, w1l, DIM, DFF);
        dim3 g2d(DIM / 32, DFF / 32, NL);
        wconv_kernel<<<g2d, blk>>>(W2, w2h, w2l, DFF, DIM);
    }

    dim3 gQKV(DIM / 128, BT / 128, 3);
    dim3 gD  (DIM / 128, BT / 128);
    dim3 gF  (DFF / 128, BT / 128);
    dim3 gAtt(SEQ / QT, BATCH * NH);
    dim3 gVc (SEQ / 32, DIM / 32, BATCH);

    for (int l = 0; l < NL; l++) {
        size_t wofs  = (size_t)l * DIM * DIM;
        size_t w1ofs = (size_t)l * DIM * DFF;

        ln_kernel<<<BT, 256>>>(x, g1 + l * DIM, be1 + l * DIM, nullptr, xnh, xnl);

        qkv_mm<<<gQKV, 256, DSM_BYTES>>>(xnh, xnl,
                                         wqh + wofs, wql + wofs,
                                         wkh + wofs, wkl + wofs,
                                         wvh + wofs, wvl + wofs,
                                         bq + l * DIM, bk + l * DIM, bv + l * DIM,
                                         q, k, v);

        ropesplit_kernel<<<(BT * NH * 32) / 256, 256>>>(q, k, qh, ql, kh, kl);
        vconv_kernel<<<gVc, dim3(32, 8)>>>(v, vth, vtl);

        attn_kernel<<<gAtt, 256, A3_BYTES>>>(qh, ql, kh, kl, vth, vtl, atth, attl);

        gemm_mm<0,1,1,0><<<gD, 256, DSM_BYTES>>>(atth, attl, woh + wofs, wol + wofs,
                                                 bo + l * DIM, x, x, nullptr, nullptr,
                                                 DIM, DIM);

        ln_kernel<<<BT, 256>>>(x, g2 + l * DIM, be2 + l * DIM, nullptr, xnh, xnl);

        gemm_mm<1,0,0,1><<<gF, 256, DSM_BYTES>>>(xnh, xnl, w1h + w1ofs, w1l + w1ofs,
                                                 b1 + l * DFF, nullptr, nullptr, hbh, hbl,
                                                 DFF, DIM);

        gemm_mm<0,1,1,0><<<gD, 256, DSM_BYTES>>>(hbh, hbl, w2h + w1ofs, w2l + w1ofs,
                                                 b2 + l * DIM, x, x, nullptr, nullptr,
                                                 DIM, DFF);
    }

    ln_kernel<<<BT, 256>>>(x, gf, bf, (float*)d_out, nullptr, nullptr);
}